// round 5
// baseline (speedup 1.0000x reference)
#include <cuda_runtime.h>
#include <cuda_bf16.h>
#include <math.h>
#include <stdint.h>

#define B_  8
#define H_  16
#define S_  1024
#define DK_ 64
#define DM_ 1024
#define M_  (B_*S_)          // 8192
#define NE  (M_*DM_)         // 8M activation elems
#define NW  (DM_*DM_)        // 1M weight elems

// ---- scratch (allocation-free rule: __device__ globals) --------------------
__device__ float g_qh[NE], g_kh[NE], g_vh[NE];
__device__ __nv_bfloat16 g_qhi[NE], g_qlo[NE];
__device__ __nv_bfloat16 g_khi[NE], g_klo[NE];
__device__ __nv_bfloat16 g_vhi[NE], g_vlo[NE];
__device__ __nv_bfloat16 g_ochi[NE], g_oclo[NE];
__device__ __nv_bfloat16 g_wqhi[NW], g_wqlo[NW];
__device__ __nv_bfloat16 g_wkhi[NW], g_wklo[NW];
__device__ __nv_bfloat16 g_wvhi[NW], g_wvlo[NW];
__device__ __nv_bfloat16 g_wfhi[NW], g_wflo[NW];

// ---- helpers ---------------------------------------------------------------
__device__ __forceinline__ uint32_t smem_u32(const void* p) {
    uint32_t a;
    asm("{ .reg .u64 t; cvta.to.shared.u64 t, %1; cvt.u32.u64 %0, t; }"
        : "=r"(a) : "l"(p));
    return a;
}

__device__ __forceinline__ void cp16(uint32_t dst, const void* src) {
    asm volatile("cp.async.cg.shared.global [%0], [%1], 16;"
                 :: "r"(dst), "l"(src));
}

__device__ __forceinline__ void ldsm4(uint32_t* r, uint32_t addr) {
    asm volatile("ldmatrix.sync.aligned.m8n8.x4.shared.b16 {%0,%1,%2,%3}, [%4];"
                 : "=r"(r[0]), "=r"(r[1]), "=r"(r[2]), "=r"(r[3]) : "r"(addr));
}

__device__ __forceinline__ void mma_bf16(float* d, const uint32_t* a, const uint32_t* b) {
    asm volatile(
        "mma.sync.aligned.m16n8k16.row.col.f32.bf16.bf16.f32 "
        "{%0,%1,%2,%3}, {%4,%5,%6,%7}, {%8,%9}, {%0,%1,%2,%3};"
        : "+f"(d[0]), "+f"(d[1]), "+f"(d[2]), "+f"(d[3])
        : "r"(a[0]), "r"(a[1]), "r"(a[2]), "r"(a[3]), "r"(b[0]), "r"(b[1]));
}

__device__ __forceinline__ void split1(float v, __nv_bfloat16& h, __nv_bfloat16& l) {
    h = __float2bfloat16(v);
    l = __float2bfloat16(v - __bfloat162float(h));
}

// ---------------------------------------------------------------------------
// batched fp32 -> (bf16 hi, bf16 lo) splitter: blockIdx.y selects tensor
// ---------------------------------------------------------------------------
__global__ __launch_bounds__(256) void split_fp32_b(
    const float* __restrict__ x0, __nv_bfloat16* __restrict__ h0, __nv_bfloat16* __restrict__ l0m,
    const float* __restrict__ x1, __nv_bfloat16* __restrict__ h1, __nv_bfloat16* __restrict__ l1m,
    const float* __restrict__ x2, __nv_bfloat16* __restrict__ h2, __nv_bfloat16* __restrict__ l2m,
    const float* __restrict__ x3, __nv_bfloat16* __restrict__ h3, __nv_bfloat16* __restrict__ l3m,
    int n4)
{
    const float* x;
    __nv_bfloat16 *hi, *lo;
    switch (blockIdx.y) {
        case 0: x = x0; hi = h0; lo = l0m; break;
        case 1: x = x1; hi = h1; lo = l1m; break;
        case 2: x = x2; hi = h2; lo = l2m; break;
        default: x = x3; hi = h3; lo = l3m; break;
    }
    if (x == nullptr) return;
    int i = blockIdx.x * blockDim.x + threadIdx.x;
    if (i >= n4) return;
    float4 v = ((const float4*)x)[i];
    __nv_bfloat16 a0, a1, a2, a3, b0, b1, b2, b3;
    split1(v.x, a0, b0); split1(v.y, a1, b1);
    split1(v.z, a2, b2); split1(v.w, a3, b3);
    ((__nv_bfloat162*)hi)[2*i]     = __halves2bfloat162(a0, a1);
    ((__nv_bfloat162*)hi)[2*i + 1] = __halves2bfloat162(a2, a3);
    ((__nv_bfloat162*)lo)[2*i]     = __halves2bfloat162(b0, b1);
    ((__nv_bfloat162*)lo)[2*i + 1] = __halves2bfloat162(b2, b3);
}

// ---------------------------------------------------------------------------
// GEMM via mma.sync (bf16, fp32 acc):
//   C[8192 x 1024] = A[8192 x 1024] * B^T (+ bias), 3-term hi/lo emulation.
// 128x128 C-tile / CTA; BK=32; 8 warps (4 M x 2 N); warp tile 32x64.
// Terms ordered Ah*Bh, Al*Bh, Ah*Bl so Bh and Ah fragments load once.
// ---------------------------------------------------------------------------
#define TS_    10240          // one tile: 128 rows * 80 B
#define STAGE_ (4*TS_)        // 40960

__global__ __launch_bounds__(256, 2) void gemm_mma(
    const __nv_bfloat16* __restrict__ Ahi, const __nv_bfloat16* __restrict__ Alo,
    const __nv_bfloat16* __restrict__ Bhi, const __nv_bfloat16* __restrict__ Blo,
    const float* __restrict__ bias, float* __restrict__ out, int bhsd_mode)
{
    extern __shared__ __align__(128) char smem[];
    const uint32_t sb = smem_u32(smem);
    const int tid = threadIdx.x, warp = tid >> 5, lane = tid & 31;
    const int wm = warp & 3, wn = warp >> 2;
    const int bm = blockIdx.y * 128, bn = blockIdx.x * 128;

    const char* src[4] = {
        (const char*)Ahi + (size_t)bm * 2048,
        (const char*)Alo + (size_t)bm * 2048,
        (const char*)Bhi + (size_t)bn * 2048,
        (const char*)Blo + (size_t)bn * 2048 };

    float acc[2][8][4];
    #pragma unroll
    for (int mi = 0; mi < 2; ++mi)
        #pragma unroll
        for (int nj = 0; nj < 8; ++nj)
            #pragma unroll
            for (int e = 0; e < 4; ++e) acc[mi][nj][e] = 0.0f;

    // ldmatrix per-lane offsets (80B padded rows -> conflict-free)
    const uint32_t offA = (uint32_t)((lane & 15) * 80 + (lane >> 4) * 16);
    const uint32_t offB = (uint32_t)(((((lane >> 4) & 1) * 8) + (lane & 7)) * 80
                                     + ((lane >> 3) & 1) * 16);

    const int lrow = tid >> 2;            // 0..63  (with it-offset covers 128)
    const int lseg = (tid & 3) * 16;      // byte segment within 64B row-chunk

    // ---- prologue: stage chunk 0 ----
    {
        #pragma unroll
        for (int t = 0; t < 4; ++t)
            #pragma unroll
            for (int it = 0; it < 2; ++it) {
                int row = lrow + it * 64;
                cp16(sb + t * TS_ + row * 80 + lseg,
                     src[t] + (size_t)row * 2048 + lseg);
            }
        asm volatile("cp.async.commit_group;");
    }

    for (int chunk = 0; chunk < 32; ++chunk) {
        if (chunk < 31) {
            const uint32_t stg = ((chunk + 1) & 1) * STAGE_;
            const int kb = (chunk + 1) * 64;
            #pragma unroll
            for (int t = 0; t < 4; ++t)
                #pragma unroll
                for (int it = 0; it < 2; ++it) {
                    int row = lrow + it * 64;
                    cp16(sb + stg + t * TS_ + row * 80 + lseg,
                         src[t] + (size_t)row * 2048 + kb + lseg);
                }
            asm volatile("cp.async.commit_group;");
            asm volatile("cp.async.wait_group 1;");
        } else {
            asm volatile("cp.async.wait_group 0;");
        }
        __syncthreads();

        const uint32_t stage = sb + (chunk & 1) * STAGE_;
        const uint32_t aHi = stage + 0 * TS_ + wm * 32 * 80 + offA;
        const uint32_t aLo = stage + 1 * TS_ + wm * 32 * 80 + offA;
        const uint32_t bHi = stage + 2 * TS_ + wn * 64 * 80 + offB;
        const uint32_t bLo = stage + 3 * TS_ + wn * 64 * 80 + offB;

        #pragma unroll
        for (int ks = 0; ks < 2; ++ks) {
            uint32_t rah[2][4], rbh[4][4];
            ldsm4(rah[0], aHi + ks * 32);
            ldsm4(rah[1], aHi + 16 * 80 + ks * 32);
            #pragma unroll
            for (int j = 0; j < 4; ++j)
                ldsm4(rbh[j], bHi + j * 16 * 80 + ks * 32);
            // term 0: Ah * Bh
            #pragma unroll
            for (int mi = 0; mi < 2; ++mi)
                #pragma unroll
                for (int nj = 0; nj < 8; ++nj)
                    mma_bf16(acc[mi][nj], rah[mi], &rbh[nj >> 1][(nj & 1) * 2]);
            // term 1: Al * Bh   (Bh frags reused)
            {
                uint32_t ral[2][4];
                ldsm4(ral[0], aLo + ks * 32);
                ldsm4(ral[1], aLo + 16 * 80 + ks * 32);
                #pragma unroll
                for (int mi = 0; mi < 2; ++mi)
                    #pragma unroll
                    for (int nj = 0; nj < 8; ++nj)
                        mma_bf16(acc[mi][nj], ral[mi], &rbh[nj >> 1][(nj & 1) * 2]);
            }
            // term 2: Ah * Bl   (Ah frags reused; Bl overwrites Bh regs)
            {
                uint32_t rbl[4][4];
                #pragma unroll
                for (int j = 0; j < 4; ++j)
                    ldsm4(rbl[j], bLo + j * 16 * 80 + ks * 32);
                #pragma unroll
                for (int mi = 0; mi < 2; ++mi)
                    #pragma unroll
                    for (int nj = 0; nj < 8; ++nj)
                        mma_bf16(acc[mi][nj], rah[mi], &rbl[nj >> 1][(nj & 1) * 2]);
            }
        }
        __syncthreads();
    }

    // ---- epilogue ----
    const int r0 = bm + wm * 32 + (lane >> 2);
    const int c0 = bn + wn * 64 + (lane & 3) * 2;
    #pragma unroll
    for (int mi = 0; mi < 2; ++mi) {
        #pragma unroll
        for (int nj = 0; nj < 8; ++nj) {
            const int gc = c0 + nj * 8;
            const float bx = bias[gc], by = bias[gc + 1];
            #pragma unroll
            for (int half = 0; half < 2; ++half) {
                const int row = r0 + mi * 16 + half * 8;
                float2 v;
                v.x = acc[mi][nj][half * 2 + 0] + bx;
                v.y = acc[mi][nj][half * 2 + 1] + by;
                if (bhsd_mode) {
                    int bb = row >> 10, ss = row & 1023;
                    int hh = gc >> 6, dk = gc & 63;
                    *(float2*)&out[(((size_t)(bb * H_ + hh)) * S_ + ss) * DK_ + dk] = v;
                } else {
                    *(float2*)&out[(size_t)row * DM_ + gc] = v;
                }
            }
        }
    }
}

// ---------------------------------------------------------------------------
// Flash-style fp32 attention per (b,h), vectorized smem traffic:
//  - K tile rows stride 68 floats (float4-aligned, conflict-free phases)
//  - V stored TRANSPOSED (Vt[dim][key], stride 68) so PV reads float4 runs
//  - Q and P read as float4 broadcasts (stride 64)
// 256 thr, 4 q-rows/warp; writes bf16 hi/lo for the final GEMM.
// ---------------------------------------------------------------------------
#define KST 68   // K/Vt row stride in floats

__global__ __launch_bounds__(256) void attn_kernel(
    const float* __restrict__ qh, const float* __restrict__ kh,
    const float* __restrict__ vh,
    __nv_bfloat16* __restrict__ ochi, __nv_bfloat16* __restrict__ oclo)
{
    extern __shared__ float sm[];
    float* Ks = sm;                 // [64][KST]  keys x dims
    float* Vt = Ks + 64*KST;        // [64][KST]  dims x keys (transposed)
    float* Qs = Vt + 64*KST;        // [32][64]
    float* Ps = Qs + 32*64;         // [32][64]

    const int tid  = threadIdx.x;
    const int warp = tid >> 5, lane = tid & 31;
    const int bh   = blockIdx.y;
    const int b    = bh >> 4, h = bh & 15;
    const int row0 = blockIdx.x * 32;

    const float* Q  = qh + (size_t)bh * S_ * DK_;
    const float* Kp = kh + (size_t)bh * S_ * DK_;
    const float* Vp = vh + (size_t)bh * S_ * DK_;

    for (int t = tid; t < 32*16; t += 256) {
        int r = t >> 4, c = (t & 15) * 4;
        float4 qv = *(const float4*)&Q[(size_t)(row0 + r)*DK_ + c];
        Qs[r*64 + c + 0] = qv.x * 0.125f;
        Qs[r*64 + c + 1] = qv.y * 0.125f;
        Qs[r*64 + c + 2] = qv.z * 0.125f;
        Qs[r*64 + c + 3] = qv.w * 0.125f;
    }

    float m[4], l[4], o0[4], o1[4];
    #pragma unroll
    for (int r = 0; r < 4; r++) { m[r] = -INFINITY; l[r] = 0.0f; o0[r] = 0.0f; o1[r] = 0.0f; }
    __syncthreads();

    for (int j0 = 0; j0 < S_; j0 += 64) {
        // load K rows; V transposed
        for (int t = tid; t < 64*16; t += 256) {
            int r = t >> 4, c = (t & 15) * 4;     // r = key, c = dim
            float4 kv = *(const float4*)&Kp[(size_t)(j0 + r)*DK_ + c];
            *(float4*)&Ks[r*KST + c] = kv;
            float4 vv = *(const float4*)&Vp[(size_t)(j0 + r)*DK_ + c];
            Vt[(c + 0)*KST + r] = vv.x;
            Vt[(c + 1)*KST + r] = vv.y;
            Vt[(c + 2)*KST + r] = vv.z;
            Vt[(c + 3)*KST + r] = vv.w;
        }
        __syncthreads();

        float s0[4], s1[4];
        #pragma unroll
        for (int r = 0; r < 4; r++) { s0[r] = 0.0f; s1[r] = 0.0f; }
        #pragma unroll
        for (int d = 0; d < 64; d += 4) {
            float4 k0 = *(const float4*)&Ks[lane*KST + d];
            float4 k1 = *(const float4*)&Ks[(lane + 32)*KST + d];
            #pragma unroll
            for (int r = 0; r < 4; r++) {
                float4 qv = *(const float4*)&Qs[(warp*4 + r)*64 + d];  // broadcast
                s0[r] += qv.x*k0.x + qv.y*k0.y + qv.z*k0.z + qv.w*k0.w;
                s1[r] += qv.x*k1.x + qv.y*k1.y + qv.z*k1.z + qv.w*k1.w;
            }
        }

        #pragma unroll
        for (int r = 0; r < 4; r++) {
            float a = s0[r], c = s1[r];
            if (a == 0.0f) a = -INFINITY;
            if (c == 0.0f) c = -INFINITY;
            float mx = fmaxf(a, c);
            #pragma unroll
            for (int off = 16; off; off >>= 1)
                mx = fmaxf(mx, __shfl_xor_sync(0xffffffffu, mx, off));
            float mnew = fmaxf(fmaxf(m[r], mx), -1e30f);
            float p0 = __expf(a - mnew);
            float p1 = __expf(c - mnew);
            float alpha = __expf(m[r] - mnew);
            float ps = p0 + p1;
            #pragma unroll
            for (int off = 16; off; off >>= 1)
                ps += __shfl_xor_sync(0xffffffffu, ps, off);
            l[r] = l[r]*alpha + ps;
            o0[r] *= alpha; o1[r] *= alpha;
            m[r] = mnew;
            Ps[(warp*4 + r)*64 + lane]      = p0;
            Ps[(warp*4 + r)*64 + lane + 32] = p1;
        }
        __syncwarp();

        // O += P @ V : lane owns output dims (lane, lane+32); float4 over keys
        #pragma unroll
        for (int j = 0; j < 64; j += 4) {
            float4 v0 = *(const float4*)&Vt[lane*KST + j];
            float4 v1 = *(const float4*)&Vt[(lane + 32)*KST + j];
            #pragma unroll
            for (int r = 0; r < 4; r++) {
                float4 p = *(const float4*)&Ps[(warp*4 + r)*64 + j];  // broadcast
                o0[r] += p.x*v0.x + p.y*v0.y + p.z*v0.z + p.w*v0.w;
                o1[r] += p.x*v1.x + p.y*v1.y + p.z*v1.z + p.w*v1.w;
            }
        }
        __syncthreads();
    }

    #pragma unroll
    for (int r = 0; r < 4; r++) {
        int grow = row0 + warp*4 + r;
        float inv = 1.0f / l[r];
        size_t base = ((size_t)b * S_ + grow) * DM_ + h * DK_;
        float v0 = o0[r] * inv;
        float v1 = o1[r] * inv;
        __nv_bfloat16 h0, l0b, h1, l1b;
        split1(v0, h0, l0b);
        split1(v1, h1, l1b);
        ochi[base + lane]      = h0;
        ochi[base + lane + 32] = h1;
        oclo[base + lane]      = l0b;
        oclo[base + lane + 32] = l1b;
    }
}

// ---------------------------------------------------------------------------

extern "C" void kernel_launch(void* const* d_in, const int* in_sizes, int n_in,
                              void* d_out, int out_size)
{
    const float* q  = (const float*)d_in[0];
    const float* k  = (const float*)d_in[1];
    const float* v  = (const float*)d_in[2];
    const float* Wq = (const float*)d_in[3];
    const float* bq = (const float*)d_in[4];
    const float* Wk = (const float*)d_in[5];
    const float* bk = (const float*)d_in[6];
    const float* Wv = (const float*)d_in[7];
    const float* bv = (const float*)d_in[8];
    const float* Wf = (const float*)d_in[9];
    const float* bf = (const float*)d_in[10];
    float* out = (float*)d_out;

    float *qh, *kh, *vh;
    __nv_bfloat16 *qhi, *qlo, *khi, *klo, *vhi, *vlo, *ochi, *oclo;
    __nv_bfloat16 *wqhi, *wqlo, *wkhi, *wklo, *wvhi, *wvlo, *wfhi, *wflo;
    cudaGetSymbolAddress((void**)&qh, g_qh);
    cudaGetSymbolAddress((void**)&kh, g_kh);
    cudaGetSymbolAddress((void**)&vh, g_vh);
    cudaGetSymbolAddress((void**)&qhi, g_qhi);   cudaGetSymbolAddress((void**)&qlo, g_qlo);
    cudaGetSymbolAddress((void**)&khi, g_khi);   cudaGetSymbolAddress((void**)&klo, g_klo);
    cudaGetSymbolAddress((void**)&vhi, g_vhi);   cudaGetSymbolAddress((void**)&vlo, g_vlo);
    cudaGetSymbolAddress((void**)&ochi, g_ochi); cudaGetSymbolAddress((void**)&oclo, g_oclo);
    cudaGetSymbolAddress((void**)&wqhi, g_wqhi); cudaGetSymbolAddress((void**)&wqlo, g_wqlo);
    cudaGetSymbolAddress((void**)&wkhi, g_wkhi); cudaGetSymbolAddress((void**)&wklo, g_wklo);
    cudaGetSymbolAddress((void**)&wvhi, g_wvhi); cudaGetSymbolAddress((void**)&wvlo, g_wvlo);
    cudaGetSymbolAddress((void**)&wfhi, g_wfhi); cudaGetSymbolAddress((void**)&wflo, g_wflo);

    // batched splits: one launch for q,k,v; one for the 4 weight matrices
    split_fp32_b<<<dim3(NE/4/256, 3), 256>>>(
        q, qhi, qlo,  k, khi, klo,  v, vhi, vlo,
        nullptr, nullptr, nullptr, NE/4);
    split_fp32_b<<<dim3(NW/4/256, 4), 256>>>(
        Wq, wqhi, wqlo,  Wk, wkhi, wklo,  Wv, wvhi, wvlo,  Wf, wfhi, wflo, NW/4);

    const int gemm_smem = 2 * STAGE_;   // 81920
    cudaFuncSetAttribute(gemm_mma, cudaFuncAttributeMaxDynamicSharedMemorySize, gemm_smem);

    dim3 gg(DM_/128, M_/128);   // (8, 64) = 512 CTAs
    gemm_mma<<<gg, 256, gemm_smem>>>(qhi, qlo, wqhi, wqlo, bq, qh, 1);
    gemm_mma<<<gg, 256, gemm_smem>>>(khi, klo, wkhi, wklo, bk, kh, 1);
    gemm_mma<<<gg, 256, gemm_smem>>>(vhi, vlo, wvhi, wvlo, bv, vh, 1);

    int attn_smem = (64*KST*2 + 32*64 + 32*64) * (int)sizeof(float);  // 51200
    cudaFuncSetAttribute(attn_kernel, cudaFuncAttributeMaxDynamicSharedMemorySize, attn_smem);
    attn_kernel<<<dim3(S_/32, B_*H_), 256, attn_smem>>>(qh, kh, vh, ochi, oclo);

    gemm_mma<<<gg, 256, gemm_smem>>>(ochi, oclo, wfhi, wflo, bf, out, 0);
}

// round 8
// speedup vs baseline: 1.0505x; 1.0505x over previous
#include <cuda_runtime.h>
#include <cuda_bf16.h>
#include <math.h>
#include <stdint.h>

#define B_  8
#define H_  16
#define S_  1024
#define DK_ 64
#define DM_ 1024
#define M_  (B_*S_)          // 8192
#define NE  (M_*DM_)         // 8M activation elems
#define NW  (DM_*DM_)        // 1M weight elems

// ---- scratch (allocation-free rule: __device__ globals) --------------------
__device__ float g_qh[NE], g_kh[NE], g_vh[NE];
__device__ __nv_bfloat16 g_qhi[NE], g_qlo[NE];
__device__ __nv_bfloat16 g_khi[NE], g_klo[NE];
__device__ __nv_bfloat16 g_vhi[NE], g_vlo[NE];
__device__ __nv_bfloat16 g_ochi[NE], g_oclo[NE];
__device__ __nv_bfloat16 g_wqhi[NW], g_wqlo[NW];
__device__ __nv_bfloat16 g_wkhi[NW], g_wklo[NW];
__device__ __nv_bfloat16 g_wvhi[NW], g_wvlo[NW];
__device__ __nv_bfloat16 g_wfhi[NW], g_wflo[NW];

// ---- helpers ---------------------------------------------------------------
__device__ __forceinline__ uint32_t smem_u32(const void* p) {
    uint32_t a;
    asm("{ .reg .u64 t; cvta.to.shared.u64 t, %1; cvt.u32.u64 %0, t; }"
        : "=r"(a) : "l"(p));
    return a;
}

__device__ __forceinline__ void cp16(uint32_t dst, const void* src) {
    asm volatile("cp.async.cg.shared.global [%0], [%1], 16;"
                 :: "r"(dst), "l"(src));
}

__device__ __forceinline__ void ldsm4(uint32_t* r, uint32_t addr) {
    asm volatile("ldmatrix.sync.aligned.m8n8.x4.shared.b16 {%0,%1,%2,%3}, [%4];"
                 : "=r"(r[0]), "=r"(r[1]), "=r"(r[2]), "=r"(r[3]) : "r"(addr));
}

__device__ __forceinline__ void mma_bf16(float* d, const uint32_t* a, const uint32_t* b) {
    asm volatile(
        "mma.sync.aligned.m16n8k16.row.col.f32.bf16.bf16.f32 "
        "{%0,%1,%2,%3}, {%4,%5,%6,%7}, {%8,%9}, {%0,%1,%2,%3};"
        : "+f"(d[0]), "+f"(d[1]), "+f"(d[2]), "+f"(d[3])
        : "r"(a[0]), "r"(a[1]), "r"(a[2]), "r"(a[3]), "r"(b[0]), "r"(b[1]));
}

__device__ __forceinline__ void split1(float v, __nv_bfloat16& h, __nv_bfloat16& l) {
    h = __float2bfloat16(v);
    l = __float2bfloat16(v - __bfloat162float(h));
}

// ---------------------------------------------------------------------------
// batched fp32 -> (bf16 hi, bf16 lo) splitter: blockIdx.y selects tensor
// ---------------------------------------------------------------------------
__global__ __launch_bounds__(256) void split_fp32_b(
    const float* __restrict__ x0, __nv_bfloat16* __restrict__ h0, __nv_bfloat16* __restrict__ l0m,
    const float* __restrict__ x1, __nv_bfloat16* __restrict__ h1, __nv_bfloat16* __restrict__ l1m,
    const float* __restrict__ x2, __nv_bfloat16* __restrict__ h2, __nv_bfloat16* __restrict__ l2m,
    const float* __restrict__ x3, __nv_bfloat16* __restrict__ h3, __nv_bfloat16* __restrict__ l3m,
    int n4)
{
    const float* x;
    __nv_bfloat16 *hi, *lo;
    switch (blockIdx.y) {
        case 0: x = x0; hi = h0; lo = l0m; break;
        case 1: x = x1; hi = h1; lo = l1m; break;
        case 2: x = x2; hi = h2; lo = l2m; break;
        default: x = x3; hi = h3; lo = l3m; break;
    }
    if (x == nullptr) return;
    int i = blockIdx.x * blockDim.x + threadIdx.x;
    if (i >= n4) return;
    float4 v = ((const float4*)x)[i];
    __nv_bfloat16 a0, a1, a2, a3, b0, b1, b2, b3;
    split1(v.x, a0, b0); split1(v.y, a1, b1);
    split1(v.z, a2, b2); split1(v.w, a3, b3);
    ((__nv_bfloat162*)hi)[2*i]     = __halves2bfloat162(a0, a1);
    ((__nv_bfloat162*)hi)[2*i + 1] = __halves2bfloat162(a2, a3);
    ((__nv_bfloat162*)lo)[2*i]     = __halves2bfloat162(b0, b1);
    ((__nv_bfloat162*)lo)[2*i + 1] = __halves2bfloat162(b2, b3);
}

// ---------------------------------------------------------------------------
// GEMM via mma.sync (bf16, fp32 acc) — unchanged from R5 (measured 163us).
// ---------------------------------------------------------------------------
#define TS_    10240          // one tile: 128 rows * 80 B
#define STAGE_ (4*TS_)        // 40960

__global__ __launch_bounds__(256, 2) void gemm_mma(
    const __nv_bfloat16* __restrict__ Ahi, const __nv_bfloat16* __restrict__ Alo,
    const __nv_bfloat16* __restrict__ Bhi, const __nv_bfloat16* __restrict__ Blo,
    const float* __restrict__ bias, float* __restrict__ out, int bhsd_mode)
{
    extern __shared__ __align__(128) char smem[];
    const uint32_t sb = smem_u32(smem);
    const int tid = threadIdx.x, warp = tid >> 5, lane = tid & 31;
    const int wm = warp & 3, wn = warp >> 2;
    const int bm = blockIdx.y * 128, bn = blockIdx.x * 128;

    const char* src[4] = {
        (const char*)Ahi + (size_t)bm * 2048,
        (const char*)Alo + (size_t)bm * 2048,
        (const char*)Bhi + (size_t)bn * 2048,
        (const char*)Blo + (size_t)bn * 2048 };

    float acc[2][8][4];
    #pragma unroll
    for (int mi = 0; mi < 2; ++mi)
        #pragma unroll
        for (int nj = 0; nj < 8; ++nj)
            #pragma unroll
            for (int e = 0; e < 4; ++e) acc[mi][nj][e] = 0.0f;

    const uint32_t offA = (uint32_t)((lane & 15) * 80 + (lane >> 4) * 16);
    const uint32_t offB = (uint32_t)(((((lane >> 4) & 1) * 8) + (lane & 7)) * 80
                                     + ((lane >> 3) & 1) * 16);

    const int lrow = tid >> 2;
    const int lseg = (tid & 3) * 16;

    {
        #pragma unroll
        for (int t = 0; t < 4; ++t)
            #pragma unroll
            for (int it = 0; it < 2; ++it) {
                int row = lrow + it * 64;
                cp16(sb + t * TS_ + row * 80 + lseg,
                     src[t] + (size_t)row * 2048 + lseg);
            }
        asm volatile("cp.async.commit_group;");
    }

    for (int chunk = 0; chunk < 32; ++chunk) {
        if (chunk < 31) {
            const uint32_t stg = ((chunk + 1) & 1) * STAGE_;
            const int kb = (chunk + 1) * 64;
            #pragma unroll
            for (int t = 0; t < 4; ++t)
                #pragma unroll
                for (int it = 0; it < 2; ++it) {
                    int row = lrow + it * 64;
                    cp16(sb + stg + t * TS_ + row * 80 + lseg,
                         src[t] + (size_t)row * 2048 + kb + lseg);
                }
            asm volatile("cp.async.commit_group;");
            asm volatile("cp.async.wait_group 1;");
        } else {
            asm volatile("cp.async.wait_group 0;");
        }
        __syncthreads();

        const uint32_t stage = sb + (chunk & 1) * STAGE_;
        const uint32_t aHi = stage + 0 * TS_ + wm * 32 * 80 + offA;
        const uint32_t aLo = stage + 1 * TS_ + wm * 32 * 80 + offA;
        const uint32_t bHi = stage + 2 * TS_ + wn * 64 * 80 + offB;
        const uint32_t bLo = stage + 3 * TS_ + wn * 64 * 80 + offB;

        #pragma unroll
        for (int ks = 0; ks < 2; ++ks) {
            uint32_t rah[2][4], rbh[4][4];
            ldsm4(rah[0], aHi + ks * 32);
            ldsm4(rah[1], aHi + 16 * 80 + ks * 32);
            #pragma unroll
            for (int j = 0; j < 4; ++j)
                ldsm4(rbh[j], bHi + j * 16 * 80 + ks * 32);
            #pragma unroll
            for (int mi = 0; mi < 2; ++mi)
                #pragma unroll
                for (int nj = 0; nj < 8; ++nj)
                    mma_bf16(acc[mi][nj], rah[mi], &rbh[nj >> 1][(nj & 1) * 2]);
            {
                uint32_t ral[2][4];
                ldsm4(ral[0], aLo + ks * 32);
                ldsm4(ral[1], aLo + 16 * 80 + ks * 32);
                #pragma unroll
                for (int mi = 0; mi < 2; ++mi)
                    #pragma unroll
                    for (int nj = 0; nj < 8; ++nj)
                        mma_bf16(acc[mi][nj], ral[mi], &rbh[nj >> 1][(nj & 1) * 2]);
            }
            {
                uint32_t rbl[4][4];
                #pragma unroll
                for (int j = 0; j < 4; ++j)
                    ldsm4(rbl[j], bLo + j * 16 * 80 + ks * 32);
                #pragma unroll
                for (int mi = 0; mi < 2; ++mi)
                    #pragma unroll
                    for (int nj = 0; nj < 8; ++nj)
                        mma_bf16(acc[mi][nj], rah[mi], &rbl[nj >> 1][(nj & 1) * 2]);
            }
        }
        __syncthreads();
    }

    const int r0 = bm + wm * 32 + (lane >> 2);
    const int c0 = bn + wn * 64 + (lane & 3) * 2;
    #pragma unroll
    for (int mi = 0; mi < 2; ++mi) {
        #pragma unroll
        for (int nj = 0; nj < 8; ++nj) {
            const int gc = c0 + nj * 8;
            const float bx = bias[gc], by = bias[gc + 1];
            #pragma unroll
            for (int half = 0; half < 2; ++half) {
                const int row = r0 + mi * 16 + half * 8;
                float2 v;
                v.x = acc[mi][nj][half * 2 + 0] + bx;
                v.y = acc[mi][nj][half * 2 + 1] + by;
                if (bhsd_mode) {
                    int bb = row >> 10, ss = row & 1023;
                    int hh = gc >> 6, dk = gc & 63;
                    *(float2*)&out[(((size_t)(bb * H_ + hh)) * S_ + ss) * DK_ + dk] = v;
                } else {
                    *(float2*)&out[(size_t)row * DM_ + gc] = v;
                }
            }
        }
    }
}

// ---------------------------------------------------------------------------
// Flash-style fp32 attention per (b,h). Row-major K/V at stride 66 floats
// (float2-aligned; lane*66 mod 32 = 2*lane -> conflict-free LDS.64 phases).
// 256 thr, 4 q-rows/warp; writes bf16 hi/lo for the final GEMM.
// ---------------------------------------------------------------------------
#define KST 66   // K/V row stride in floats

__global__ __launch_bounds__(256) void attn_kernel(
    const float* __restrict__ qh, const float* __restrict__ kh,
    const float* __restrict__ vh,
    __nv_bfloat16* __restrict__ ochi, __nv_bfloat16* __restrict__ oclo)
{
    extern __shared__ float sm[];
    float* Ks = sm;                 // [64][KST]
    float* Vs = Ks + 64*KST;        // [64][KST]
    float* Qs = Vs + 64*KST;        // [32][64]
    float* Ps = Qs + 32*64;         // [32][64]

    const int tid  = threadIdx.x;
    const int warp = tid >> 5, lane = tid & 31;
    const int bh   = blockIdx.y;
    const int b    = bh >> 4, h = bh & 15;
    const int row0 = blockIdx.x * 32;

    const float* Q  = qh + (size_t)bh * S_ * DK_;
    const float* Kp = kh + (size_t)bh * S_ * DK_;
    const float* Vp = vh + (size_t)bh * S_ * DK_;

    for (int t = tid; t < 32*16; t += 256) {
        int r = t >> 4, c = (t & 15) * 4;
        float4 qv = *(const float4*)&Q[(size_t)(row0 + r)*DK_ + c];
        Qs[r*64 + c + 0] = qv.x * 0.125f;
        Qs[r*64 + c + 1] = qv.y * 0.125f;
        Qs[r*64 + c + 2] = qv.z * 0.125f;
        Qs[r*64 + c + 3] = qv.w * 0.125f;
    }

    float m[4], l[4], o0[4], o1[4];
    #pragma unroll
    for (int r = 0; r < 4; r++) { m[r] = -INFINITY; l[r] = 0.0f; o0[r] = 0.0f; o1[r] = 0.0f; }
    __syncthreads();

    for (int j0 = 0; j0 < S_; j0 += 64) {
        for (int t = tid; t < 64*16; t += 256) {
            int r = t >> 4, c = (t & 15) * 4;
            float4 kv = *(const float4*)&Kp[(size_t)(j0 + r)*DK_ + c];
            *(float2*)&Ks[r*KST + c]     = make_float2(kv.x, kv.y);
            *(float2*)&Ks[r*KST + c + 2] = make_float2(kv.z, kv.w);
            float4 vv = *(const float4*)&Vp[(size_t)(j0 + r)*DK_ + c];
            *(float2*)&Vs[r*KST + c]     = make_float2(vv.x, vv.y);
            *(float2*)&Vs[r*KST + c + 2] = make_float2(vv.z, vv.w);
        }
        __syncthreads();

        float s0[4], s1[4];
        #pragma unroll
        for (int r = 0; r < 4; r++) { s0[r] = 0.0f; s1[r] = 0.0f; }
        #pragma unroll
        for (int d = 0; d < 64; d += 2) {
            float2 k0 = *(const float2*)&Ks[lane*KST + d];
            float2 k1 = *(const float2*)&Ks[(lane + 32)*KST + d];
            #pragma unroll
            for (int r = 0; r < 4; r++) {
                float2 qv = *(const float2*)&Qs[(warp*4 + r)*64 + d];  // broadcast
                s0[r] += qv.x*k0.x + qv.y*k0.y;
                s1[r] += qv.x*k1.x + qv.y*k1.y;
            }
        }

        #pragma unroll
        for (int r = 0; r < 4; r++) {
            float a = s0[r], c = s1[r];
            if (a == 0.0f) a = -INFINITY;
            if (c == 0.0f) c = -INFINITY;
            float mx = fmaxf(a, c);
            #pragma unroll
            for (int off = 16; off; off >>= 1)
                mx = fmaxf(mx, __shfl_xor_sync(0xffffffffu, mx, off));
            float mnew = fmaxf(fmaxf(m[r], mx), -1e30f);
            float p0 = __expf(a - mnew);
            float p1 = __expf(c - mnew);
            float alpha = __expf(m[r] - mnew);
            float ps = p0 + p1;
            #pragma unroll
            for (int off = 16; off; off >>= 1)
                ps += __shfl_xor_sync(0xffffffffu, ps, off);
            l[r] = l[r]*alpha + ps;
            o0[r] *= alpha; o1[r] *= alpha;
            m[r] = mnew;
            Ps[(warp*4 + r)*64 + lane]      = p0;
            Ps[(warp*4 + r)*64 + lane + 32] = p1;
        }
        __syncwarp();

        // O += P @ V : lane owns dims (lane, lane+32); float2 over key pairs
        #pragma unroll
        for (int j = 0; j < 64; j += 2) {
            float va0 = Vs[j*KST + lane];
            float vb0 = Vs[(j + 1)*KST + lane];
            float va1 = Vs[j*KST + lane + 32];
            float vb1 = Vs[(j + 1)*KST + lane + 32];
            #pragma unroll
            for (int r = 0; r < 4; r++) {
                float2 p = *(const float2*)&Ps[(warp*4 + r)*64 + j];  // broadcast
                o0[r] += p.x*va0 + p.y*vb0;
                o1[r] += p.x*va1 + p.y*vb1;
            }
        }
        __syncthreads();
    }

    #pragma unroll
    for (int r = 0; r < 4; r++) {
        int grow = row0 + warp*4 + r;
        float inv = 1.0f / l[r];
        size_t base = ((size_t)b * S_ + grow) * DM_ + h * DK_;
        float v0 = o0[r] * inv;
        float v1 = o1[r] * inv;
        __nv_bfloat16 h0, l0b, h1, l1b;
        split1(v0, h0, l0b);
        split1(v1, h1, l1b);
        ochi[base + lane]      = h0;
        ochi[base + lane + 32] = h1;
        oclo[base + lane]      = l0b;
        oclo[base + lane + 32] = l1b;
    }
}

// ---------------------------------------------------------------------------

extern "C" void kernel_launch(void* const* d_in, const int* in_sizes, int n_in,
                              void* d_out, int out_size)
{
    const float* q  = (const float*)d_in[0];
    const float* k  = (const float*)d_in[1];
    const float* v  = (const float*)d_in[2];
    const float* Wq = (const float*)d_in[3];
    const float* bq = (const float*)d_in[4];
    const float* Wk = (const float*)d_in[5];
    const float* bk = (const float*)d_in[6];
    const float* Wv = (const float*)d_in[7];
    const float* bv = (const float*)d_in[8];
    const float* Wf = (const float*)d_in[9];
    const float* bf = (const float*)d_in[10];
    float* out = (float*)d_out;

    float *qh, *kh, *vh;
    __nv_bfloat16 *qhi, *qlo, *khi, *klo, *vhi, *vlo, *ochi, *oclo;
    __nv_bfloat16 *wqhi, *wqlo, *wkhi, *wklo, *wvhi, *wvlo, *wfhi, *wflo;
    cudaGetSymbolAddress((void**)&qh, g_qh);
    cudaGetSymbolAddress((void**)&kh, g_kh);
    cudaGetSymbolAddress((void**)&vh, g_vh);
    cudaGetSymbolAddress((void**)&qhi, g_qhi);   cudaGetSymbolAddress((void**)&qlo, g_qlo);
    cudaGetSymbolAddress((void**)&khi, g_khi);   cudaGetSymbolAddress((void**)&klo, g_klo);
    cudaGetSymbolAddress((void**)&vhi, g_vhi);   cudaGetSymbolAddress((void**)&vlo, g_vlo);
    cudaGetSymbolAddress((void**)&ochi, g_ochi); cudaGetSymbolAddress((void**)&oclo, g_oclo);
    cudaGetSymbolAddress((void**)&wqhi, g_wqhi); cudaGetSymbolAddress((void**)&wqlo, g_wqlo);
    cudaGetSymbolAddress((void**)&wkhi, g_wkhi); cudaGetSymbolAddress((void**)&wklo, g_wklo);
    cudaGetSymbolAddress((void**)&wvhi, g_wvhi); cudaGetSymbolAddress((void**)&wvlo, g_wvlo);
    cudaGetSymbolAddress((void**)&wfhi, g_wfhi); cudaGetSymbolAddress((void**)&wflo, g_wflo);

    split_fp32_b<<<dim3(NE/4/256, 3), 256>>>(
        q, qhi, qlo,  k, khi, klo,  v, vhi, vlo,
        nullptr, nullptr, nullptr, NE/4);
    split_fp32_b<<<dim3(NW/4/256, 4), 256>>>(
        Wq, wqhi, wqlo,  Wk, wkhi, wklo,  Wv, wvhi, wvlo,  Wf, wfhi, wflo, NW/4);

    const int gemm_smem = 2 * STAGE_;   // 81920
    cudaFuncSetAttribute(gemm_mma, cudaFuncAttributeMaxDynamicSharedMemorySize, gemm_smem);

    dim3 gg(DM_/128, M_/128);   // (8, 64) = 512 CTAs
    gemm_mma<<<gg, 256, gemm_smem>>>(qhi, qlo, wqhi, wqlo, bq, qh, 1);
    gemm_mma<<<gg, 256, gemm_smem>>>(khi, klo, wkhi, wklo, bk, kh, 1);
    gemm_mma<<<gg, 256, gemm_smem>>>(vhi, vlo, wvhi, wvlo, bv, vh, 1);

    int attn_smem = (64*KST*2 + 32*64 + 32*64) * (int)sizeof(float);  // 50176
    cudaFuncSetAttribute(attn_kernel, cudaFuncAttributeMaxDynamicSharedMemorySize, attn_smem);
    attn_kernel<<<dim3(S_/32, B_*H_), 256, attn_smem>>>(qh, kh, vh, ochi, oclo);

    gemm_mma<<<gg, 256, gemm_smem>>>(ochi, oclo, wfhi, wflo, bf, out, 0);
}

// round 9
// speedup vs baseline: 1.9294x; 1.8368x over previous
#include <cuda_runtime.h>
#include <cuda_bf16.h>
#include <math.h>
#include <stdint.h>

#define B_  8
#define H_  16
#define S_  1024
#define DK_ 64
#define DM_ 1024
#define M_  (B_*S_)          // 8192
#define NE  (M_*DM_)         // 8M activation elems
#define NW  (DM_*DM_)        // 1M weight elems

// ---- scratch (allocation-free rule: __device__ globals) --------------------
// split inputs
__device__ __nv_bfloat16 g_xqh[NE], g_xql[NE];
__device__ __nv_bfloat16 g_xkh[NE], g_xkl[NE];
__device__ __nv_bfloat16 g_xvh[NE], g_xvl[NE];
// projected per-head tensors (bf16 hi/lo)
__device__ __nv_bfloat16 g_pqh[NE], g_pql[NE];   // Q/8   [bh][s][dk]
__device__ __nv_bfloat16 g_pkh[NE], g_pkl[NE];   // K     [bh][s][dk]
__device__ __nv_bfloat16 g_pvh[NE], g_pvl[NE];   // V^T   [bh][dk][s]
// attention output (concat layout)
__device__ __nv_bfloat16 g_och[NE], g_ocl[NE];
// split weights
__device__ __nv_bfloat16 g_wqh[NW], g_wql[NW];
__device__ __nv_bfloat16 g_wkh[NW], g_wkl[NW];
__device__ __nv_bfloat16 g_wvh[NW], g_wvl[NW];
__device__ __nv_bfloat16 g_wfh[NW], g_wfl[NW];

// ---- helpers ---------------------------------------------------------------
__device__ __forceinline__ uint32_t smem_u32(const void* p) {
    uint32_t a;
    asm("{ .reg .u64 t; cvta.to.shared.u64 t, %1; cvt.u32.u64 %0, t; }"
        : "=r"(a) : "l"(p));
    return a;
}

__device__ __forceinline__ void cp16(uint32_t dst, const void* src) {
    asm volatile("cp.async.cg.shared.global [%0], [%1], 16;"
                 :: "r"(dst), "l"(src));
}

__device__ __forceinline__ void ldsm4(uint32_t* r, uint32_t addr) {
    asm volatile("ldmatrix.sync.aligned.m8n8.x4.shared.b16 {%0,%1,%2,%3}, [%4];"
                 : "=r"(r[0]), "=r"(r[1]), "=r"(r[2]), "=r"(r[3]) : "r"(addr));
}

__device__ __forceinline__ void mma_bf16(float* d, const uint32_t* a, const uint32_t* b) {
    asm volatile(
        "mma.sync.aligned.m16n8k16.row.col.f32.bf16.bf16.f32 "
        "{%0,%1,%2,%3}, {%4,%5,%6,%7}, {%8,%9}, {%0,%1,%2,%3};"
        : "+f"(d[0]), "+f"(d[1]), "+f"(d[2]), "+f"(d[3])
        : "r"(a[0]), "r"(a[1]), "r"(a[2]), "r"(a[3]), "r"(b[0]), "r"(b[1]));
}

__device__ __forceinline__ void split1(float v, __nv_bfloat16& h, __nv_bfloat16& l) {
    h = __float2bfloat16(v);
    l = __float2bfloat16(v - __bfloat162float(h));
}

// pack two floats into (hi bf16x2, lo bf16x2)
__device__ __forceinline__ void split_pack2(float x, float y, uint32_t& hi, uint32_t& lo) {
    __nv_bfloat16 hx, lx, hy, ly;
    split1(x, hx, lx);
    split1(y, hy, ly);
    __nv_bfloat162 th = __halves2bfloat162(hx, hy);
    __nv_bfloat162 tl = __halves2bfloat162(lx, ly);
    hi = *(uint32_t*)&th;
    lo = *(uint32_t*)&tl;
}

// ---------------------------------------------------------------------------
// batched fp32 -> (bf16 hi, bf16 lo) splitter: blockIdx.y selects tensor
// ---------------------------------------------------------------------------
__global__ __launch_bounds__(256) void split_fp32_b(
    const float* __restrict__ x0, __nv_bfloat16* __restrict__ h0, __nv_bfloat16* __restrict__ l0m,
    const float* __restrict__ x1, __nv_bfloat16* __restrict__ h1, __nv_bfloat16* __restrict__ l1m,
    const float* __restrict__ x2, __nv_bfloat16* __restrict__ h2, __nv_bfloat16* __restrict__ l2m,
    const float* __restrict__ x3, __nv_bfloat16* __restrict__ h3, __nv_bfloat16* __restrict__ l3m,
    int n4)
{
    const float* x;
    __nv_bfloat16 *hi, *lo;
    switch (blockIdx.y) {
        case 0: x = x0; hi = h0; lo = l0m; break;
        case 1: x = x1; hi = h1; lo = l1m; break;
        case 2: x = x2; hi = h2; lo = l2m; break;
        default: x = x3; hi = h3; lo = l3m; break;
    }
    if (x == nullptr) return;
    int i = blockIdx.x * blockDim.x + threadIdx.x;
    if (i >= n4) return;
    float4 v = ((const float4*)x)[i];
    uint32_t ha, la, hb, lb;
    split_pack2(v.x, v.y, ha, la);
    split_pack2(v.z, v.w, hb, lb);
    ((uint32_t*)hi)[2*i]     = ha;
    ((uint32_t*)hi)[2*i + 1] = hb;
    ((uint32_t*)lo)[2*i]     = la;
    ((uint32_t*)lo)[2*i + 1] = lb;
}

// ---------------------------------------------------------------------------
// GEMM via mma.sync (bf16, fp32 acc): mainloop unchanged from R5 (163us).
// Epilogue modes: 0 = fp32 row-major (+bias)
//                 1 = Q: (acc+bias)/8 -> hi/lo [bh][s][dk]
//                 2 = K: (acc+bias)   -> hi/lo [bh][s][dk]
//                 3 = V: (acc+bias)   -> hi/lo TRANSPOSED [bh][dk][s]
// ---------------------------------------------------------------------------
#define TS_    10240          // one tile: 128 rows * 80 B
#define STAGE_ (4*TS_)        // 40960

__global__ __launch_bounds__(256, 2) void gemm_mma(
    const __nv_bfloat16* __restrict__ Ahi, const __nv_bfloat16* __restrict__ Alo,
    const __nv_bfloat16* __restrict__ Bhi, const __nv_bfloat16* __restrict__ Blo,
    const float* __restrict__ bias, float* __restrict__ outf,
    __nv_bfloat16* __restrict__ outh, __nv_bfloat16* __restrict__ outl, int mode)
{
    extern __shared__ __align__(128) char smem[];
    const uint32_t sb = smem_u32(smem);
    const int tid = threadIdx.x, warp = tid >> 5, lane = tid & 31;
    const int wm = warp & 3, wn = warp >> 2;
    const int bm = blockIdx.y * 128, bn = blockIdx.x * 128;

    const char* src[4] = {
        (const char*)Ahi + (size_t)bm * 2048,
        (const char*)Alo + (size_t)bm * 2048,
        (const char*)Bhi + (size_t)bn * 2048,
        (const char*)Blo + (size_t)bn * 2048 };

    float acc[2][8][4];
    #pragma unroll
    for (int mi = 0; mi < 2; ++mi)
        #pragma unroll
        for (int nj = 0; nj < 8; ++nj)
            #pragma unroll
            for (int e = 0; e < 4; ++e) acc[mi][nj][e] = 0.0f;

    const uint32_t offA = (uint32_t)((lane & 15) * 80 + (lane >> 4) * 16);
    const uint32_t offB = (uint32_t)(((((lane >> 4) & 1) * 8) + (lane & 7)) * 80
                                     + ((lane >> 3) & 1) * 16);

    const int lrow = tid >> 2;
    const int lseg = (tid & 3) * 16;

    {
        #pragma unroll
        for (int t = 0; t < 4; ++t)
            #pragma unroll
            for (int it = 0; it < 2; ++it) {
                int row = lrow + it * 64;
                cp16(sb + t * TS_ + row * 80 + lseg,
                     src[t] + (size_t)row * 2048 + lseg);
            }
        asm volatile("cp.async.commit_group;");
    }

    #pragma unroll 1
    for (int chunk = 0; chunk < 32; ++chunk) {
        if (chunk < 31) {
            const uint32_t stg = ((chunk + 1) & 1) * STAGE_;
            const int kb = (chunk + 1) * 64;
            #pragma unroll
            for (int t = 0; t < 4; ++t)
                #pragma unroll
                for (int it = 0; it < 2; ++it) {
                    int row = lrow + it * 64;
                    cp16(sb + stg + t * TS_ + row * 80 + lseg,
                         src[t] + (size_t)row * 2048 + kb + lseg);
                }
            asm volatile("cp.async.commit_group;");
            asm volatile("cp.async.wait_group 1;");
        } else {
            asm volatile("cp.async.wait_group 0;");
        }
        __syncthreads();

        const uint32_t stage = sb + (chunk & 1) * STAGE_;
        const uint32_t aHi = stage + 0 * TS_ + wm * 32 * 80 + offA;
        const uint32_t aLo = stage + 1 * TS_ + wm * 32 * 80 + offA;
        const uint32_t bHi = stage + 2 * TS_ + wn * 64 * 80 + offB;
        const uint32_t bLo = stage + 3 * TS_ + wn * 64 * 80 + offB;

        #pragma unroll
        for (int ks = 0; ks < 2; ++ks) {
            uint32_t rah[2][4], rbh[4][4];
            ldsm4(rah[0], aHi + ks * 32);
            ldsm4(rah[1], aHi + 16 * 80 + ks * 32);
            #pragma unroll
            for (int j = 0; j < 4; ++j)
                ldsm4(rbh[j], bHi + j * 16 * 80 + ks * 32);
            #pragma unroll
            for (int mi = 0; mi < 2; ++mi)
                #pragma unroll
                for (int nj = 0; nj < 8; ++nj)
                    mma_bf16(acc[mi][nj], rah[mi], &rbh[nj >> 1][(nj & 1) * 2]);
            {
                uint32_t ral[2][4];
                ldsm4(ral[0], aLo + ks * 32);
                ldsm4(ral[1], aLo + 16 * 80 + ks * 32);
                #pragma unroll
                for (int mi = 0; mi < 2; ++mi)
                    #pragma unroll
                    for (int nj = 0; nj < 8; ++nj)
                        mma_bf16(acc[mi][nj], ral[mi], &rbh[nj >> 1][(nj & 1) * 2]);
            }
            {
                uint32_t rbl[4][4];
                #pragma unroll
                for (int j = 0; j < 4; ++j)
                    ldsm4(rbl[j], bLo + j * 16 * 80 + ks * 32);
                #pragma unroll
                for (int mi = 0; mi < 2; ++mi)
                    #pragma unroll
                    for (int nj = 0; nj < 8; ++nj)
                        mma_bf16(acc[mi][nj], rah[mi], &rbl[nj >> 1][(nj & 1) * 2]);
            }
        }
        __syncthreads();
    }

    // ---- epilogue ----
    const int r0 = bm + wm * 32 + (lane >> 2);
    const int c0 = bn + wn * 64 + (lane & 3) * 2;
    const float sc = (mode == 1) ? 0.125f : 1.0f;
    #pragma unroll
    for (int mi = 0; mi < 2; ++mi) {
        #pragma unroll
        for (int nj = 0; nj < 8; ++nj) {
            const int gc = c0 + nj * 8;
            const float bx = bias[gc], by = bias[gc + 1];
            #pragma unroll
            for (int half = 0; half < 2; ++half) {
                const int row = r0 + mi * 16 + half * 8;
                float vx = acc[mi][nj][half * 2 + 0] + bx;
                float vy = acc[mi][nj][half * 2 + 1] + by;
                if (mode == 0) {
                    float2 v = make_float2(vx, vy);
                    *(float2*)&outf[(size_t)row * DM_ + gc] = v;
                } else {
                    vx *= sc; vy *= sc;
                    const int bb = row >> 10, ss = row & 1023;
                    const int hh = gc >> 6, dk = gc & 63;
                    if (mode <= 2) {
                        uint32_t hp, lp;
                        split_pack2(vx, vy, hp, lp);
                        size_t idx = (((size_t)(bb * H_ + hh)) * S_ + ss) * DK_ + dk;
                        *(uint32_t*)&outh[idx] = hp;
                        *(uint32_t*)&outl[idx] = lp;
                    } else {
                        __nv_bfloat16 hx, lx, hy, ly;
                        split1(vx, hx, lx);
                        split1(vy, hy, ly);
                        size_t idx = (((size_t)(bb * H_ + hh)) * DK_ + dk) * S_ + ss;
                        outh[idx] = hx;         outl[idx] = lx;
                        outh[idx + S_] = hy;    outl[idx + S_] = ly;
                    }
                }
            }
        }
    }
}

// ---------------------------------------------------------------------------
// FlashAttention-2 style attention on mma.sync, hi/lo 3-term for QK^T and PV.
// CTA: 128 q-rows x 8 warps (m16 each), K-tiles of 64 keys, double-buffered.
// Q pre-scaled by 1/8 in projection epilogue. V stored transposed globally so
// both MMAs use the verified non-trans ldmatrix B pattern.
// ---------------------------------------------------------------------------
#define RB    144            // smem row: 64 bf16 = 128B data + 16B pad
#define TILEB (64*RB)        // 9216
#define BUFB  (4*TILEB)      // 36864 (kh, kl, vh, vl)
#define QSTG  (128*RB)       // 18432

__global__ __launch_bounds__(256) void attn_mma(
    const __nv_bfloat16* __restrict__ pqh, const __nv_bfloat16* __restrict__ pql,
    const __nv_bfloat16* __restrict__ pkh, const __nv_bfloat16* __restrict__ pkl,
    const __nv_bfloat16* __restrict__ pvh, const __nv_bfloat16* __restrict__ pvl,
    __nv_bfloat16* __restrict__ och, __nv_bfloat16* __restrict__ ocl)
{
    extern __shared__ __align__(128) char smem[];
    const uint32_t sb = smem_u32(smem);
    const int tid = threadIdx.x, w = tid >> 5, lane = tid & 31;
    const int bh = blockIdx.y, b = bh >> 4, h = bh & 15;
    const int row0 = blockIdx.x * 128;

    const uint32_t offA = (uint32_t)((lane & 15) * RB + (lane >> 4) * 16);
    const uint32_t offB = (uint32_t)(((((lane >> 4) & 1) * 8) + (lane & 7)) * RB
                                     + ((lane >> 3) & 1) * 16);

    // ---- stage Q hi/lo, extract A fragments ----
    {
        const char* qh_src = (const char*)(pqh + ((size_t)bh * S_ + row0) * DK_);
        const char* ql_src = (const char*)(pql + ((size_t)bh * S_ + row0) * DK_);
        #pragma unroll
        for (int i = 0; i < 8; ++i) {
            int idx = tid + i * 256;
            int mat = idx >> 10, rem = idx & 1023, row = rem >> 3, seg = rem & 7;
            const char* s = (mat ? ql_src : qh_src) + (size_t)row * 128 + seg * 16;
            cp16(sb + mat * QSTG + row * RB + seg * 16, s);
        }
        asm volatile("cp.async.commit_group;");
        asm volatile("cp.async.wait_group 0;");
        __syncthreads();
    }
    uint32_t qfh[4][4], qfl[4][4];
    #pragma unroll
    for (int ks = 0; ks < 4; ++ks) {
        ldsm4(qfh[ks], sb + w * 16 * RB + offA + ks * 32);
        ldsm4(qfl[ks], sb + QSTG + w * 16 * RB + offA + ks * 32);
    }
    __syncthreads();

    float oacc[8][4];
    #pragma unroll
    for (int j = 0; j < 8; ++j)
        #pragma unroll
        for (int e = 0; e < 4; ++e) oacc[j][e] = 0.0f;
    float m0 = -INFINITY, m1 = -INFINITY, l0 = 0.0f, l1 = 0.0f;

    const char* kh_src = (const char*)(pkh + (size_t)bh * S_ * DK_);
    const char* kl_src = (const char*)(pkl + (size_t)bh * S_ * DK_);
    const char* vh_src = (const char*)(pvh + (size_t)bh * DK_ * S_);
    const char* vl_src = (const char*)(pvl + (size_t)bh * DK_ * S_);

    // prefetch K-tile 0
    #pragma unroll
    for (int i = 0; i < 8; ++i) {
        int idx = tid + i * 256;
        int tile = idx >> 9, rem = idx & 511, row = rem >> 3, seg = rem & 7;
        const char* s;
        if (tile == 0)      s = kh_src + (size_t)row * 128 + seg * 16;
        else if (tile == 1) s = kl_src + (size_t)row * 128 + seg * 16;
        else if (tile == 2) s = vh_src + (size_t)row * 2048 + seg * 16;
        else                s = vl_src + (size_t)row * 2048 + seg * 16;
        cp16(sb + tile * TILEB + row * RB + seg * 16, s);
    }
    asm volatile("cp.async.commit_group;");

    #pragma unroll 1
    for (int t = 0; t < 16; ++t) {
        asm volatile("cp.async.wait_group 0;");
        __syncthreads();
        const uint32_t buf = sb + (t & 1) * BUFB;
        if (t < 15) {
            const uint32_t nbuf = sb + ((t + 1) & 1) * BUFB;
            const int kb = (t + 1) * 64;
            #pragma unroll
            for (int i = 0; i < 8; ++i) {
                int idx = tid + i * 256;
                int tile = idx >> 9, rem = idx & 511, row = rem >> 3, seg = rem & 7;
                const char* s;
                if (tile == 0)      s = kh_src + (size_t)(kb + row) * 128 + seg * 16;
                else if (tile == 1) s = kl_src + (size_t)(kb + row) * 128 + seg * 16;
                else if (tile == 2) s = vh_src + (size_t)row * 2048 + kb * 2 + seg * 16;
                else                s = vl_src + (size_t)row * 2048 + kb * 2 + seg * 16;
                cp16(nbuf + tile * TILEB + row * RB + seg * 16, s);
            }
            asm volatile("cp.async.commit_group;");
        }

        // ---- S = Q K^T (3-term) ----
        float sa[8][4];
        #pragma unroll
        for (int j = 0; j < 8; ++j)
            #pragma unroll
            for (int e = 0; e < 4; ++e) sa[j][e] = 0.0f;

        #pragma unroll
        for (int ks = 0; ks < 4; ++ks) {
            #pragma unroll
            for (int np = 0; np < 4; ++np) {
                uint32_t f[4], g[4];
                ldsm4(f, buf + np * 16 * RB + offB + ks * 32);
                mma_bf16(sa[2*np],   qfh[ks], f);
                mma_bf16(sa[2*np+1], qfh[ks], f + 2);
                mma_bf16(sa[2*np],   qfl[ks], f);
                mma_bf16(sa[2*np+1], qfl[ks], f + 2);
                ldsm4(g, buf + TILEB + np * 16 * RB + offB + ks * 32);
                mma_bf16(sa[2*np],   qfh[ks], g);
                mma_bf16(sa[2*np+1], qfh[ks], g + 2);
            }
        }

        // ---- mask + online softmax ----
        float mx0 = -INFINITY, mx1 = -INFINITY;
        #pragma unroll
        for (int j = 0; j < 8; ++j) {
            #pragma unroll
            for (int e = 0; e < 4; ++e)
                if (sa[j][e] == 0.0f) sa[j][e] = -INFINITY;
            mx0 = fmaxf(mx0, fmaxf(sa[j][0], sa[j][1]));
            mx1 = fmaxf(mx1, fmaxf(sa[j][2], sa[j][3]));
        }
        mx0 = fmaxf(mx0, __shfl_xor_sync(0xffffffffu, mx0, 1));
        mx0 = fmaxf(mx0, __shfl_xor_sync(0xffffffffu, mx0, 2));
        mx1 = fmaxf(mx1, __shfl_xor_sync(0xffffffffu, mx1, 1));
        mx1 = fmaxf(mx1, __shfl_xor_sync(0xffffffffu, mx1, 2));

        float mn0 = fmaxf(fmaxf(m0, mx0), -1e30f);
        float mn1 = fmaxf(fmaxf(m1, mx1), -1e30f);
        float a0 = __expf(m0 - mn0), a1 = __expf(m1 - mn1);
        m0 = mn0; m1 = mn1;

        float rs0 = 0.0f, rs1 = 0.0f;
        #pragma unroll
        for (int j = 0; j < 8; ++j) {
            sa[j][0] = __expf(sa[j][0] - m0);
            sa[j][1] = __expf(sa[j][1] - m0);
            sa[j][2] = __expf(sa[j][2] - m1);
            sa[j][3] = __expf(sa[j][3] - m1);
            rs0 += sa[j][0] + sa[j][1];
            rs1 += sa[j][2] + sa[j][3];
        }
        rs0 += __shfl_xor_sync(0xffffffffu, rs0, 1);
        rs0 += __shfl_xor_sync(0xffffffffu, rs0, 2);
        rs1 += __shfl_xor_sync(0xffffffffu, rs1, 1);
        rs1 += __shfl_xor_sync(0xffffffffu, rs1, 2);
        l0 = l0 * a0 + rs0;
        l1 = l1 * a1 + rs1;

        #pragma unroll
        for (int j = 0; j < 8; ++j) {
            oacc[j][0] *= a0; oacc[j][1] *= a0;
            oacc[j][2] *= a1; oacc[j][3] *= a1;
        }

        // ---- P fragments (hi/lo) from accumulator pairs ----
        uint32_t ph[4][4], pl[4][4];
        #pragma unroll
        for (int tt = 0; tt < 4; ++tt) {
            split_pack2(sa[2*tt][0],   sa[2*tt][1],   ph[tt][0], pl[tt][0]);
            split_pack2(sa[2*tt][2],   sa[2*tt][3],   ph[tt][1], pl[tt][1]);
            split_pack2(sa[2*tt+1][0], sa[2*tt+1][1], ph[tt][2], pl[tt][2]);
            split_pack2(sa[2*tt+1][2], sa[2*tt+1][3], ph[tt][3], pl[tt][3]);
        }

        // ---- O += P V (3-term), V^T tiles ----
        #pragma unroll
        for (int ks = 0; ks < 4; ++ks) {
            #pragma unroll
            for (int np = 0; np < 4; ++np) {
                uint32_t f[4], g[4];
                ldsm4(f, buf + 2 * TILEB + np * 16 * RB + offB + ks * 32);
                mma_bf16(oacc[2*np],   ph[ks], f);
                mma_bf16(oacc[2*np+1], ph[ks], f + 2);
                mma_bf16(oacc[2*np],   pl[ks], f);
                mma_bf16(oacc[2*np+1], pl[ks], f + 2);
                ldsm4(g, buf + 3 * TILEB + np * 16 * RB + offB + ks * 32);
                mma_bf16(oacc[2*np],   ph[ks], g);
                mma_bf16(oacc[2*np+1], ph[ks], g + 2);
            }
        }
    }

    // ---- normalize + store (concat layout, bf16 hi/lo) ----
    const float i0 = 1.0f / l0, i1 = 1.0f / l1;
    const int r = lane >> 2, c = (lane & 3) * 2;
    const int grow0 = row0 + w * 16 + r;
    const size_t base0 = ((size_t)b * S_ + grow0) * DM_ + h * DK_;
    const size_t base1 = ((size_t)b * S_ + grow0 + 8) * DM_ + h * DK_;
    #pragma unroll
    for (int nt = 0; nt < 8; ++nt) {
        const int gc = nt * 8 + c;
        uint32_t hp, lp;
        split_pack2(oacc[nt][0] * i0, oacc[nt][1] * i0, hp, lp);
        *(uint32_t*)&och[base0 + gc] = hp;
        *(uint32_t*)&ocl[base0 + gc] = lp;
        split_pack2(oacc[nt][2] * i1, oacc[nt][3] * i1, hp, lp);
        *(uint32_t*)&och[base1 + gc] = hp;
        *(uint32_t*)&ocl[base1 + gc] = lp;
    }
}

// ---------------------------------------------------------------------------

extern "C" void kernel_launch(void* const* d_in, const int* in_sizes, int n_in,
                              void* d_out, int out_size)
{
    const float* q  = (const float*)d_in[0];
    const float* k  = (const float*)d_in[1];
    const float* v  = (const float*)d_in[2];
    const float* Wq = (const float*)d_in[3];
    const float* bq = (const float*)d_in[4];
    const float* Wk = (const float*)d_in[5];
    const float* bk = (const float*)d_in[6];
    const float* Wv = (const float*)d_in[7];
    const float* bv = (const float*)d_in[8];
    const float* Wf = (const float*)d_in[9];
    const float* bf = (const float*)d_in[10];
    float* out = (float*)d_out;

    __nv_bfloat16 *xqh, *xql, *xkh, *xkl, *xvh, *xvl;
    __nv_bfloat16 *pqh, *pql, *pkh, *pkl, *pvh, *pvl, *och, *ocl;
    __nv_bfloat16 *wqh, *wql, *wkh, *wkl, *wvh, *wvl, *wfh, *wfl;
    cudaGetSymbolAddress((void**)&xqh, g_xqh); cudaGetSymbolAddress((void**)&xql, g_xql);
    cudaGetSymbolAddress((void**)&xkh, g_xkh); cudaGetSymbolAddress((void**)&xkl, g_xkl);
    cudaGetSymbolAddress((void**)&xvh, g_xvh); cudaGetSymbolAddress((void**)&xvl, g_xvl);
    cudaGetSymbolAddress((void**)&pqh, g_pqh); cudaGetSymbolAddress((void**)&pql, g_pql);
    cudaGetSymbolAddress((void**)&pkh, g_pkh); cudaGetSymbolAddress((void**)&pkl, g_pkl);
    cudaGetSymbolAddress((void**)&pvh, g_pvh); cudaGetSymbolAddress((void**)&pvl, g_pvl);
    cudaGetSymbolAddress((void**)&och, g_och); cudaGetSymbolAddress((void**)&ocl, g_ocl);
    cudaGetSymbolAddress((void**)&wqh, g_wqh); cudaGetSymbolAddress((void**)&wql, g_wql);
    cudaGetSymbolAddress((void**)&wkh, g_wkh); cudaGetSymbolAddress((void**)&wkl, g_wkl);
    cudaGetSymbolAddress((void**)&wvh, g_wvh); cudaGetSymbolAddress((void**)&wvl, g_wvl);
    cudaGetSymbolAddress((void**)&wfh, g_wfh); cudaGetSymbolAddress((void**)&wfl, g_wfl);

    split_fp32_b<<<dim3(NE/4/256, 3), 256>>>(
        q, xqh, xql,  k, xkh, xkl,  v, xvh, xvl,
        nullptr, nullptr, nullptr, NE/4);
    split_fp32_b<<<dim3(NW/4/256, 4), 256>>>(
        Wq, wqh, wql,  Wk, wkh, wkl,  Wv, wvh, wvl,  Wf, wfh, wfl, NW/4);

    const int gemm_smem = 2 * STAGE_;   // 81920
    cudaFuncSetAttribute(gemm_mma, cudaFuncAttributeMaxDynamicSharedMemorySize, gemm_smem);

    dim3 gg(DM_/128, M_/128);   // (8, 64) = 512 CTAs
    gemm_mma<<<gg, 256, gemm_smem>>>(xqh, xql, wqh, wql, bq, nullptr, pqh, pql, 1);
    gemm_mma<<<gg, 256, gemm_smem>>>(xkh, xkl, wkh, wkl, bk, nullptr, pkh, pkl, 2);
    gemm_mma<<<gg, 256, gemm_smem>>>(xvh, xvl, wvh, wvl, bv, nullptr, pvh, pvl, 3);

    const int attn_smem = 2 * BUFB;     // 73728
    cudaFuncSetAttribute(attn_mma, cudaFuncAttributeMaxDynamicSharedMemorySize, attn_smem);
    attn_mma<<<dim3(S_/128, B_*H_), 256, attn_smem>>>(
        pqh, pql, pkh, pkl, pvh, pvl, och, ocl);

    gemm_mma<<<gg, 256, gemm_smem>>>(och, ocl, wfh, wfl, bf, out, nullptr, nullptr, 0);
}

// round 13
// speedup vs baseline: 2.7714x; 1.4363x over previous
#include <cuda_runtime.h>
#include <cuda_fp16.h>
#include <math.h>
#include <stdint.h>

#define B_  8
#define H_  16
#define S_  1024
#define DK_ 64
#define DM_ 1024
#define M_  (B_*S_)          // 8192
#define NE  (M_*DM_)         // 8M activation elems
#define NW  (DM_*DM_)        // 1M weight elems

// ---- scratch (allocation-free rule: __device__ globals) --------------------
// fp16 activations (hi only — A-side of 2-term GEMMs)
__device__ __half g_xqh[NE], g_xkh[NE], g_xvh[NE];
// projected per-head tensors
__device__ __half g_pqh[NE];               // Q/8   [bh][s][dk]  hi only
__device__ __half g_pkh[NE], g_pkl[NE];    // K     [bh][s][dk]  hi/lo
__device__ __half g_pvh[NE], g_pvl[NE];    // V^T   [bh][dk][s]  hi/lo
// attention output (concat layout, hi only — A-side of final GEMM)
__device__ __half g_och[NE];
// split weights (hi/lo — B-side)
__device__ __half g_wqh[NW], g_wql[NW];
__device__ __half g_wkh[NW], g_wkl[NW];
__device__ __half g_wvh[NW], g_wvl[NW];
__device__ __half g_wfh[NW], g_wfl[NW];

// ---- helpers ---------------------------------------------------------------
__device__ __forceinline__ uint32_t smem_u32(const void* p) {
    uint32_t a;
    asm("{ .reg .u64 t; cvta.to.shared.u64 t, %1; cvt.u32.u64 %0, t; }"
        : "=r"(a) : "l"(p));
    return a;
}

__device__ __forceinline__ void cp16(uint32_t dst, const void* src) {
    asm volatile("cp.async.cg.shared.global [%0], [%1], 16;"
                 :: "r"(dst), "l"(src));
}

__device__ __forceinline__ void ldsm4(uint32_t* r, uint32_t addr) {
    asm volatile("ldmatrix.sync.aligned.m8n8.x4.shared.b16 {%0,%1,%2,%3}, [%4];"
                 : "=r"(r[0]), "=r"(r[1]), "=r"(r[2]), "=r"(r[3]) : "r"(addr));
}

__device__ __forceinline__ void mma_f16(float* d, const uint32_t* a, const uint32_t* b) {
    asm volatile(
        "mma.sync.aligned.m16n8k16.row.col.f32.f16.f16.f32 "
        "{%0,%1,%2,%3}, {%4,%5,%6,%7}, {%8,%9}, {%0,%1,%2,%3};"
        : "+f"(d[0]), "+f"(d[1]), "+f"(d[2]), "+f"(d[3])
        : "r"(a[0]), "r"(a[1]), "r"(a[2]), "r"(a[3]), "r"(b[0]), "r"(b[1]));
}

__device__ __forceinline__ uint32_t pack2h(float x, float y) {
    __half2 t = __halves2half2(__float2half_rn(x), __float2half_rn(y));
    return *(uint32_t*)&t;
}

__device__ __forceinline__ void split1h(float v, __half& h, __half& l) {
    h = __float2half_rn(v);
    l = __float2half_rn(v - __half2float(h));
}

__device__ __forceinline__ void split_pack2h(float x, float y, uint32_t& hi, uint32_t& lo) {
    __half hx, lx, hy, ly;
    split1h(x, hx, lx);
    split1h(y, hy, ly);
    __half2 th = __halves2half2(hx, hy);
    __half2 tl = __halves2half2(lx, ly);
    hi = *(uint32_t*)&th;
    lo = *(uint32_t*)&tl;
}

// ---------------------------------------------------------------------------
// activations: fp32 -> fp16 (hi only). blockIdx.y selects tensor.
// ---------------------------------------------------------------------------
__global__ __launch_bounds__(256) void conv_fp16_b(
    const float* __restrict__ x0, __half* __restrict__ h0,
    const float* __restrict__ x1, __half* __restrict__ h1,
    const float* __restrict__ x2, __half* __restrict__ h2, int n4)
{
    const float* x;
    __half* hi;
    switch (blockIdx.y) {
        case 0: x = x0; hi = h0; break;
        case 1: x = x1; hi = h1; break;
        default: x = x2; hi = h2; break;
    }
    int i = blockIdx.x * blockDim.x + threadIdx.x;
    if (i >= n4) return;
    float4 v = ((const float4*)x)[i];
    ((uint32_t*)hi)[2*i]     = pack2h(v.x, v.y);
    ((uint32_t*)hi)[2*i + 1] = pack2h(v.z, v.w);
}

// ---------------------------------------------------------------------------
// weights: fp32 -> (fp16 hi, fp16 lo). blockIdx.y selects tensor.
// ---------------------------------------------------------------------------
__global__ __launch_bounds__(256) void split_fp16_b(
    const float* __restrict__ x0, __half* __restrict__ h0, __half* __restrict__ l0m,
    const float* __restrict__ x1, __half* __restrict__ h1, __half* __restrict__ l1m,
    const float* __restrict__ x2, __half* __restrict__ h2, __half* __restrict__ l2m,
    const float* __restrict__ x3, __half* __restrict__ h3, __half* __restrict__ l3m,
    int n4)
{
    const float* x;
    __half *hi, *lo;
    switch (blockIdx.y) {
        case 0: x = x0; hi = h0; lo = l0m; break;
        case 1: x = x1; hi = h1; lo = l1m; break;
        case 2: x = x2; hi = h2; lo = l2m; break;
        default: x = x3; hi = h3; lo = l3m; break;
    }
    int i = blockIdx.x * blockDim.x + threadIdx.x;
    if (i >= n4) return;
    float4 v = ((const float4*)x)[i];
    uint32_t ha, la, hb, lb;
    split_pack2h(v.x, v.y, ha, la);
    split_pack2h(v.z, v.w, hb, lb);
    ((uint32_t*)hi)[2*i]     = ha;
    ((uint32_t*)hi)[2*i + 1] = hb;
    ((uint32_t*)lo)[2*i]     = la;
    ((uint32_t*)lo)[2*i + 1] = lb;
}

// ---------------------------------------------------------------------------
// 2-term GEMM via mma.sync fp16: C = Ah*(Bh+Bl)^T (+bias).
// 128x128 C-tile / CTA; BK=32; 8 warps (4M x 2N); warp tile 32x64.
// Smem: 2 stages x 3 tiles (Ah, Bh, Bl) of 128 rows x 80B.
// Epilogue modes: 0 = fp32 row-major
//                 1 = Q: (acc+bias)/8 -> fp16 hi [bh][s][dk]
//                 2 = K: (acc+bias)   -> fp16 hi/lo [bh][s][dk]
//                 3 = V: (acc+bias)   -> fp16 hi/lo TRANSPOSED [bh][dk][s]
// ---------------------------------------------------------------------------
#define TS_    10240          // one tile: 128 rows * 80 B
#define STAGE_ (3*TS_)        // 30720

__global__ __launch_bounds__(256, 2) void gemm_mma(
    const __half* __restrict__ Ah, const __half* __restrict__ Bh,
    const __half* __restrict__ Bl,
    const float* __restrict__ bias, float* __restrict__ outf,
    __half* __restrict__ outh, __half* __restrict__ outl, int mode)
{
    extern __shared__ __align__(128) char smem[];
    const uint32_t sb = smem_u32(smem);
    const int tid = threadIdx.x, warp = tid >> 5, lane = tid & 31;
    const int wm = warp & 3, wn = warp >> 2;
    const int bm = blockIdx.y * 128, bn = blockIdx.x * 128;

    const char* src[3] = {
        (const char*)(Ah + (size_t)bm * DM_),
        (const char*)(Bh + (size_t)bn * DM_),
        (const char*)(Bl + (size_t)bn * DM_) };

    float acc[2][8][4];
    #pragma unroll
    for (int mi = 0; mi < 2; ++mi)
        #pragma unroll
        for (int nj = 0; nj < 8; ++nj)
            #pragma unroll
            for (int e = 0; e < 4; ++e) acc[mi][nj][e] = 0.0f;

    const uint32_t offA = (uint32_t)((lane & 15) * 80 + (lane >> 4) * 16);
    const uint32_t offB = (uint32_t)(((((lane >> 4) & 1) * 8) + (lane & 7)) * 80
                                     + ((lane >> 3) & 1) * 16);

    const int lrow = tid >> 2;            // 0..63 (it covers 128)
    const int lseg = (tid & 3) * 16;

    {
        #pragma unroll
        for (int t = 0; t < 3; ++t)
            #pragma unroll
            for (int it = 0; it < 2; ++it) {
                int row = lrow + it * 64;
                cp16(sb + t * TS_ + row * 80 + lseg,
                     src[t] + (size_t)row * 2048 + lseg);
            }
        asm volatile("cp.async.commit_group;");
    }

    #pragma unroll 1
    for (int chunk = 0; chunk < 32; ++chunk) {
        if (chunk < 31) {
            const uint32_t stg = ((chunk + 1) & 1) * STAGE_;
            const int kb = (chunk + 1) * 64;
            #pragma unroll
            for (int t = 0; t < 3; ++t)
                #pragma unroll
                for (int it = 0; it < 2; ++it) {
                    int row = lrow + it * 64;
                    cp16(sb + stg + t * TS_ + row * 80 + lseg,
                         src[t] + (size_t)row * 2048 + kb + lseg);
                }
            asm volatile("cp.async.commit_group;");
            asm volatile("cp.async.wait_group 1;");
        } else {
            asm volatile("cp.async.wait_group 0;");
        }
        __syncthreads();

        const uint32_t stage = sb + (chunk & 1) * STAGE_;
        const uint32_t aHi = stage + 0 * TS_ + wm * 32 * 80 + offA;
        const uint32_t bHi = stage + 1 * TS_ + wn * 64 * 80 + offB;
        const uint32_t bLo = stage + 2 * TS_ + wn * 64 * 80 + offB;

        #pragma unroll
        for (int ks = 0; ks < 2; ++ks) {
            uint32_t rah[2][4], rb[4][4];
            ldsm4(rah[0], aHi + ks * 32);
            ldsm4(rah[1], aHi + 16 * 80 + ks * 32);
            #pragma unroll
            for (int j = 0; j < 4; ++j)
                ldsm4(rb[j], bHi + j * 16 * 80 + ks * 32);
            #pragma unroll
            for (int mi = 0; mi < 2; ++mi)
                #pragma unroll
                for (int nj = 0; nj < 8; ++nj)
                    mma_f16(acc[mi][nj], rah[mi], &rb[nj >> 1][(nj & 1) * 2]);
            #pragma unroll
            for (int j = 0; j < 4; ++j)
                ldsm4(rb[j], bLo + j * 16 * 80 + ks * 32);
            #pragma unroll
            for (int mi = 0; mi < 2; ++mi)
                #pragma unroll
                for (int nj = 0; nj < 8; ++nj)
                    mma_f16(acc[mi][nj], rah[mi], &rb[nj >> 1][(nj & 1) * 2]);
        }
        __syncthreads();
    }

    // ---- epilogue ----
    const int r0 = bm + wm * 32 + (lane >> 2);
    const int c0 = bn + wn * 64 + (lane & 3) * 2;
    const float sc = (mode == 1) ? 0.125f : 1.0f;
    #pragma unroll
    for (int mi = 0; mi < 2; ++mi) {
        #pragma unroll
        for (int nj = 0; nj < 8; ++nj) {
            const int gc = c0 + nj * 8;
            const float bx = bias[gc], by = bias[gc + 1];
            #pragma unroll
            for (int half = 0; half < 2; ++half) {
                const int row = r0 + mi * 16 + half * 8;
                float vx = acc[mi][nj][half * 2 + 0] + bx;
                float vy = acc[mi][nj][half * 2 + 1] + by;
                if (mode == 0) {
                    float2 v = make_float2(vx, vy);
                    *(float2*)&outf[(size_t)row * DM_ + gc] = v;
                } else {
                    vx *= sc; vy *= sc;
                    const int bb = row >> 10, ss = row & 1023;
                    const int hh = gc >> 6, dk = gc & 63;
                    if (mode == 1) {
                        size_t idx = (((size_t)(bb * H_ + hh)) * S_ + ss) * DK_ + dk;
                        *(uint32_t*)&outh[idx] = pack2h(vx, vy);
                    } else if (mode == 2) {
                        uint32_t hp, lp;
                        split_pack2h(vx, vy, hp, lp);
                        size_t idx = (((size_t)(bb * H_ + hh)) * S_ + ss) * DK_ + dk;
                        *(uint32_t*)&outh[idx] = hp;
                        *(uint32_t*)&outl[idx] = lp;
                    } else {
                        __half hx, lx, hy, ly;
                        split1h(vx, hx, lx);
                        split1h(vy, hy, ly);
                        size_t idx = (((size_t)(bb * H_ + hh)) * DK_ + dk) * S_ + ss;
                        outh[idx] = hx;         outl[idx] = lx;
                        outh[idx + S_] = hy;    outl[idx + S_] = ly;
                    }
                }
            }
        }
    }
}

// ---------------------------------------------------------------------------
// FlashAttention-2 on mma.sync fp16, 2-term (hi-A x hi/lo-B) for QK^T and PV.
// CTA: 128 q-rows x 8 warps (m16 each), K-tiles of 64 keys, double-buffered.
// ---------------------------------------------------------------------------
#define RB    144            // smem row: 64 fp16 = 128B data + 16B pad
#define TILEB (64*RB)        // 9216
#define BUFB  (4*TILEB)      // 36864 (kh, kl, vh, vl)

__global__ __launch_bounds__(256) void attn_mma(
    const __half* __restrict__ pqh,
    const __half* __restrict__ pkh, const __half* __restrict__ pkl,
    const __half* __restrict__ pvh, const __half* __restrict__ pvl,
    __half* __restrict__ och)
{
    extern __shared__ __align__(128) char smem[];
    const uint32_t sb = smem_u32(smem);
    const int tid = threadIdx.x, w = tid >> 5, lane = tid & 31;
    const int bh = blockIdx.y, b = bh >> 4, h = bh & 15;
    const int row0 = blockIdx.x * 128;

    const uint32_t offA = (uint32_t)((lane & 15) * RB + (lane >> 4) * 16);
    const uint32_t offB = (uint32_t)(((((lane >> 4) & 1) * 8) + (lane & 7)) * RB
                                     + ((lane >> 3) & 1) * 16);

    // ---- stage Q (hi only), extract A fragments ----
    {
        const char* q_src = (const char*)(pqh + ((size_t)bh * S_ + row0) * DK_);
        #pragma unroll
        for (int i = 0; i < 4; ++i) {
            int idx = tid + i * 256;            // 0..1023
            int row = idx >> 3, seg = idx & 7;
            cp16(sb + row * RB + seg * 16, q_src + (size_t)row * 128 + seg * 16);
        }
        asm volatile("cp.async.commit_group;");
        asm volatile("cp.async.wait_group 0;");
        __syncthreads();
    }
    uint32_t qf[4][4];
    #pragma unroll
    for (int ks = 0; ks < 4; ++ks)
        ldsm4(qf[ks], sb + w * 16 * RB + offA + ks * 32);
    __syncthreads();

    float oacc[8][4];
    #pragma unroll
    for (int j = 0; j < 8; ++j)
        #pragma unroll
        for (int e = 0; e < 4; ++e) oacc[j][e] = 0.0f;
    float m0 = -INFINITY, m1 = -INFINITY, l0 = 0.0f, l1 = 0.0f;

    const char* kh_src = (const char*)(pkh + (size_t)bh * S_ * DK_);
    const char* kl_src = (const char*)(pkl + (size_t)bh * S_ * DK_);
    const char* vh_src = (const char*)(pvh + (size_t)bh * DK_ * S_);
    const char* vl_src = (const char*)(pvl + (size_t)bh * DK_ * S_);

    // prefetch K-tile 0
    #pragma unroll
    for (int i = 0; i < 8; ++i) {
        int idx = tid + i * 256;
        int tile = idx >> 9, rem = idx & 511, row = rem >> 3, seg = rem & 7;
        const char* s;
        if (tile == 0)      s = kh_src + (size_t)row * 128 + seg * 16;
        else if (tile == 1) s = kl_src + (size_t)row * 128 + seg * 16;
        else if (tile == 2) s = vh_src + (size_t)row * 2048 + seg * 16;
        else                s = vl_src + (size_t)row * 2048 + seg * 16;
        cp16(sb + tile * TILEB + row * RB + seg * 16, s);
    }
    asm volatile("cp.async.commit_group;");

    #pragma unroll 1
    for (int t = 0; t < 16; ++t) {
        asm volatile("cp.async.wait_group 0;");
        __syncthreads();
        const uint32_t buf = sb + (t & 1) * BUFB;
        if (t < 15) {
            const uint32_t nbuf = sb + ((t + 1) & 1) * BUFB;
            const int kb = (t + 1) * 64;
            #pragma unroll
            for (int i = 0; i < 8; ++i) {
                int idx = tid + i * 256;
                int tile = idx >> 9, rem = idx & 511, row = rem >> 3, seg = rem & 7;
                const char* s;
                if (tile == 0)      s = kh_src + (size_t)(kb + row) * 128 + seg * 16;
                else if (tile == 1) s = kl_src + (size_t)(kb + row) * 128 + seg * 16;
                else if (tile == 2) s = vh_src + (size_t)row * 2048 + kb * 2 + seg * 16;
                else                s = vl_src + (size_t)row * 2048 + kb * 2 + seg * 16;
                cp16(nbuf + tile * TILEB + row * RB + seg * 16, s);
            }
            asm volatile("cp.async.commit_group;");
        }

        // ---- S = Q K^T (2-term: Qh*Kh + Qh*Kl) ----
        float sa[8][4];
        #pragma unroll
        for (int j = 0; j < 8; ++j)
            #pragma unroll
            for (int e = 0; e < 4; ++e) sa[j][e] = 0.0f;

        #pragma unroll
        for (int ks = 0; ks < 4; ++ks) {
            #pragma unroll
            for (int np = 0; np < 4; ++np) {
                uint32_t f[4], g[4];
                ldsm4(f, buf + np * 16 * RB + offB + ks * 32);
                mma_f16(sa[2*np],   qf[ks], f);
                mma_f16(sa[2*np+1], qf[ks], f + 2);
                ldsm4(g, buf + TILEB + np * 16 * RB + offB + ks * 32);
                mma_f16(sa[2*np],   qf[ks], g);
                mma_f16(sa[2*np+1], qf[ks], g + 2);
            }
        }

        // ---- mask + online softmax ----
        float mx0 = -INFINITY, mx1 = -INFINITY;
        #pragma unroll
        for (int j = 0; j < 8; ++j) {
            #pragma unroll
            for (int e = 0; e < 4; ++e)
                if (sa[j][e] == 0.0f) sa[j][e] = -INFINITY;
            mx0 = fmaxf(mx0, fmaxf(sa[j][0], sa[j][1]));
            mx1 = fmaxf(mx1, fmaxf(sa[j][2], sa[j][3]));
        }
        mx0 = fmaxf(mx0, __shfl_xor_sync(0xffffffffu, mx0, 1));
        mx0 = fmaxf(mx0, __shfl_xor_sync(0xffffffffu, mx0, 2));
        mx1 = fmaxf(mx1, __shfl_xor_sync(0xffffffffu, mx1, 1));
        mx1 = fmaxf(mx1, __shfl_xor_sync(0xffffffffu, mx1, 2));

        float mn0 = fmaxf(fmaxf(m0, mx0), -1e30f);
        float mn1 = fmaxf(fmaxf(m1, mx1), -1e30f);
        float a0 = __expf(m0 - mn0), a1 = __expf(m1 - mn1);
        m0 = mn0; m1 = mn1;

        float rs0 = 0.0f, rs1 = 0.0f;
        #pragma unroll
        for (int j = 0; j < 8; ++j) {
            sa[j][0] = __expf(sa[j][0] - m0);
            sa[j][1] = __expf(sa[j][1] - m0);
            sa[j][2] = __expf(sa[j][2] - m1);
            sa[j][3] = __expf(sa[j][3] - m1);
            rs0 += sa[j][0] + sa[j][1];
            rs1 += sa[j][2] + sa[j][3];
        }
        rs0 += __shfl_xor_sync(0xffffffffu, rs0, 1);
        rs0 += __shfl_xor_sync(0xffffffffu, rs0, 2);
        rs1 += __shfl_xor_sync(0xffffffffu, rs1, 1);
        rs1 += __shfl_xor_sync(0xffffffffu, rs1, 2);
        l0 = l0 * a0 + rs0;
        l1 = l1 * a1 + rs1;

        #pragma unroll
        for (int j = 0; j < 8; ++j) {
            oacc[j][0] *= a0; oacc[j][1] *= a0;
            oacc[j][2] *= a1; oacc[j][3] *= a1;
        }

        // ---- P fragments (hi only) ----
        uint32_t ph[4][4];
        #pragma unroll
        for (int tt = 0; tt < 4; ++tt) {
            ph[tt][0] = pack2h(sa[2*tt][0],   sa[2*tt][1]);
            ph[tt][1] = pack2h(sa[2*tt][2],   sa[2*tt][3]);
            ph[tt][2] = pack2h(sa[2*tt+1][0], sa[2*tt+1][1]);
            ph[tt][3] = pack2h(sa[2*tt+1][2], sa[2*tt+1][3]);
        }

        // ---- O += P V (2-term: Ph*Vh + Ph*Vl), V^T tiles ----
        #pragma unroll
        for (int ks = 0; ks < 4; ++ks) {
            #pragma unroll
            for (int np = 0; np < 4; ++np) {
                uint32_t f[4], g[4];
                ldsm4(f, buf + 2 * TILEB + np * 16 * RB + offB + ks * 32);
                mma_f16(oacc[2*np],   ph[ks], f);
                mma_f16(oacc[2*np+1], ph[ks], f + 2);
                ldsm4(g, buf + 3 * TILEB + np * 16 * RB + offB + ks * 32);
                mma_f16(oacc[2*np],   ph[ks], g);
                mma_f16(oacc[2*np+1], ph[ks], g + 2);
            }
        }
    }

    // ---- normalize + store (concat layout, fp16 hi) ----
    const float i0 = 1.0f / l0, i1 = 1.0f / l1;
    const int r = lane >> 2, c = (lane & 3) * 2;
    const int grow0 = row0 + w * 16 + r;
    const size_t base0 = ((size_t)b * S_ + grow0) * DM_ + h * DK_;
    const size_t base1 = ((size_t)b * S_ + grow0 + 8) * DM_ + h * DK_;
    #pragma unroll
    for (int nt = 0; nt < 8; ++nt) {
        const int gc = nt * 8 + c;
        *(uint32_t*)&och[base0 + gc] = pack2h(oacc[nt][0] * i0, oacc[nt][1] * i0);
        *(uint32_t*)&och[base1 + gc] = pack2h(oacc[nt][2] * i1, oacc[nt][3] * i1);
    }
}

// ---------------------------------------------------------------------------

extern "C" void kernel_launch(void* const* d_in, const int* in_sizes, int n_in,
                              void* d_out, int out_size)
{
    const float* q  = (const float*)d_in[0];
    const float* k  = (const float*)d_in[1];
    const float* v  = (const float*)d_in[2];
    const float* Wq = (const float*)d_in[3];
    const float* bq = (const float*)d_in[4];
    const float* Wk = (const float*)d_in[5];
    const float* bk = (const float*)d_in[6];
    const float* Wv = (const float*)d_in[7];
    const float* bv = (const float*)d_in[8];
    const float* Wf = (const float*)d_in[9];
    const float* bf = (const float*)d_in[10];
    float* out = (float*)d_out;

    __half *xqh, *xkh, *xvh;
    __half *pqh, *pkh, *pkl, *pvh, *pvl, *och;
    __half *wqh, *wql, *wkh, *wkl, *wvh, *wvl, *wfh, *wfl;
    cudaGetSymbolAddress((void**)&xqh, g_xqh);
    cudaGetSymbolAddress((void**)&xkh, g_xkh);
    cudaGetSymbolAddress((void**)&xvh, g_xvh);
    cudaGetSymbolAddress((void**)&pqh, g_pqh);
    cudaGetSymbolAddress((void**)&pkh, g_pkh); cudaGetSymbolAddress((void**)&pkl, g_pkl);
    cudaGetSymbolAddress((void**)&pvh, g_pvh); cudaGetSymbolAddress((void**)&pvl, g_pvl);
    cudaGetSymbolAddress((void**)&och, g_och);
    cudaGetSymbolAddress((void**)&wqh, g_wqh); cudaGetSymbolAddress((void**)&wql, g_wql);
    cudaGetSymbolAddress((void**)&wkh, g_wkh); cudaGetSymbolAddress((void**)&wkl, g_wkl);
    cudaGetSymbolAddress((void**)&wvh, g_wvh); cudaGetSymbolAddress((void**)&wvl, g_wvl);
    cudaGetSymbolAddress((void**)&wfh, g_wfh); cudaGetSymbolAddress((void**)&wfl, g_wfl);

    conv_fp16_b<<<dim3(NE/4/256, 3), 256>>>(q, xqh, k, xkh, v, xvh, NE/4);
    split_fp16_b<<<dim3(NW/4/256, 4), 256>>>(
        Wq, wqh, wql,  Wk, wkh, wkl,  Wv, wvh, wvl,  Wf, wfh, wfl, NW/4);

    const int gemm_smem = 2 * STAGE_;   // 61440
    cudaFuncSetAttribute(gemm_mma, cudaFuncAttributeMaxDynamicSharedMemorySize, gemm_smem);

    dim3 gg(DM_/128, M_/128);   // (8, 64) = 512 CTAs
    gemm_mma<<<gg, 256, gemm_smem>>>(xqh, wqh, wql, bq, nullptr, pqh, nullptr, 1);
    gemm_mma<<<gg, 256, gemm_smem>>>(xkh, wkh, wkl, bk, nullptr, pkh, pkl, 2);
    gemm_mma<<<gg, 256, gemm_smem>>>(xvh, wvh, wvl, bv, nullptr, pvh, pvl, 3);

    const int attn_smem = 2 * BUFB;     // 73728
    cudaFuncSetAttribute(attn_mma, cudaFuncAttributeMaxDynamicSharedMemorySize, attn_smem);
    attn_mma<<<dim3(S_/128, B_*H_), 256, attn_smem>>>(
        pqh, pkh, pkl, pvh, pvl, och);

    gemm_mma<<<gg, 256, gemm_smem>>>(och, wfh, wfl, bf, out, nullptr, nullptr, 0);
}

// round 15
// speedup vs baseline: 2.9305x; 1.0574x over previous
#include <cuda_runtime.h>
#include <cuda_fp16.h>
#include <math.h>
#include <stdint.h>

#define B_  8
#define H_  16
#define S_  1024
#define DK_ 64
#define DM_ 1024
#define M_  (B_*S_)          // 8192
#define NE  (M_*DM_)         // 8M activation elems
#define NW  (DM_*DM_)        // 1M weight elems

// ---- scratch (allocation-free rule: __device__ globals) --------------------
__device__ __half g_xqh[NE], g_xkh[NE], g_xvh[NE];
__device__ __half g_pqh[NE];               // Q/8   [bh][s][dk]  hi only
__device__ __half g_pkh[NE], g_pkl[NE];    // K     [bh][s][dk]  hi/lo
__device__ __half g_pvh[NE], g_pvl[NE];    // V^T   [bh][dk][s]  hi/lo
__device__ __half g_och[NE];               // attention out (concat), hi only
__device__ __half g_wqh[NW], g_wql[NW];
__device__ __half g_wkh[NW], g_wkl[NW];
__device__ __half g_wvh[NW], g_wvl[NW];
__device__ __half g_wfh[NW], g_wfl[NW];

// ---- helpers ---------------------------------------------------------------
__device__ __forceinline__ uint32_t smem_u32(const void* p) {
    uint32_t a;
    asm("{ .reg .u64 t; cvta.to.shared.u64 t, %1; cvt.u32.u64 %0, t; }"
        : "=r"(a) : "l"(p));
    return a;
}

__device__ __forceinline__ void cp16(uint32_t dst, const void* src) {
    asm volatile("cp.async.cg.shared.global [%0], [%1], 16;"
                 :: "r"(dst), "l"(src));
}

__device__ __forceinline__ void ldsm4(uint32_t* r, uint32_t addr) {
    asm volatile("ldmatrix.sync.aligned.m8n8.x4.shared.b16 {%0,%1,%2,%3}, [%4];"
                 : "=r"(r[0]), "=r"(r[1]), "=r"(r[2]), "=r"(r[3]) : "r"(addr));
}

__device__ __forceinline__ void mma_f16(float* d, const uint32_t* a, const uint32_t* b) {
    asm volatile(
        "mma.sync.aligned.m16n8k16.row.col.f32.f16.f16.f32 "
        "{%0,%1,%2,%3}, {%4,%5,%6,%7}, {%8,%9}, {%0,%1,%2,%3};"
        : "+f"(d[0]), "+f"(d[1]), "+f"(d[2]), "+f"(d[3])
        : "r"(a[0]), "r"(a[1]), "r"(a[2]), "r"(a[3]), "r"(b[0]), "r"(b[1]));
}

__device__ __forceinline__ uint32_t pack2h(float x, float y) {
    __half2 t = __halves2half2(__float2half_rn(x), __float2half_rn(y));
    return *(uint32_t*)&t;
}

__device__ __forceinline__ void split1h(float v, __half& h, __half& l) {
    h = __float2half_rn(v);
    l = __float2half_rn(v - __half2float(h));
}

__device__ __forceinline__ void split_pack2h(float x, float y, uint32_t& hi, uint32_t& lo) {
    __half hx, lx, hy, ly;
    split1h(x, hx, lx);
    split1h(y, hy, ly);
    __half2 th = __halves2half2(hx, hy);
    __half2 tl = __halves2half2(lx, ly);
    hi = *(uint32_t*)&th;
    lo = *(uint32_t*)&tl;
}

// ---------------------------------------------------------------------------
// activations: fp32 -> fp16 (hi only). blockIdx.y selects tensor.
// ---------------------------------------------------------------------------
__global__ __launch_bounds__(256) void conv_fp16_b(
    const float* __restrict__ x0, __half* __restrict__ h0,
    const float* __restrict__ x1, __half* __restrict__ h1,
    const float* __restrict__ x2, __half* __restrict__ h2, int n4)
{
    const float* x;
    __half* hi;
    switch (blockIdx.y) {
        case 0: x = x0; hi = h0; break;
        case 1: x = x1; hi = h1; break;
        default: x = x2; hi = h2; break;
    }
    int i = blockIdx.x * blockDim.x + threadIdx.x;
    if (i >= n4) return;
    float4 v = ((const float4*)x)[i];
    ((uint32_t*)hi)[2*i]     = pack2h(v.x, v.y);
    ((uint32_t*)hi)[2*i + 1] = pack2h(v.z, v.w);
}

// ---------------------------------------------------------------------------
// weights: fp32 -> (fp16 hi, fp16 lo). blockIdx.y selects tensor.
// ---------------------------------------------------------------------------
__global__ __launch_bounds__(256) void split_fp16_b(
    const float* __restrict__ x0, __half* __restrict__ h0, __half* __restrict__ l0m,
    const float* __restrict__ x1, __half* __restrict__ h1, __half* __restrict__ l1m,
    const float* __restrict__ x2, __half* __restrict__ h2, __half* __restrict__ l2m,
    const float* __restrict__ x3, __half* __restrict__ h3, __half* __restrict__ l3m,
    int n4)
{
    const float* x;
    __half *hi, *lo;
    switch (blockIdx.y) {
        case 0: x = x0; hi = h0; lo = l0m; break;
        case 1: x = x1; hi = h1; lo = l1m; break;
        case 2: x = x2; hi = h2; lo = l2m; break;
        default: x = x3; hi = h3; lo = l3m; break;
    }
    int i = blockIdx.x * blockDim.x + threadIdx.x;
    if (i >= n4) return;
    float4 v = ((const float4*)x)[i];
    uint32_t ha, la, hb, lb;
    split_pack2h(v.x, v.y, ha, la);
    split_pack2h(v.z, v.w, hb, lb);
    ((uint32_t*)hi)[2*i]     = ha;
    ((uint32_t*)hi)[2*i + 1] = hb;
    ((uint32_t*)lo)[2*i]     = la;
    ((uint32_t*)lo)[2*i + 1] = lb;
}

// ---------------------------------------------------------------------------
// 2-term GEMM via mma.sync fp16: C = Ah*(Bh+Bl)^T (+bias).
// 128x128 C-tile / CTA; BK=32; 8 warps (4M x 2N); warp tile 32x64.
// 3-stage cp.async pipeline; loads for chunk c+2 issued before compute of c.
// blockIdx.z selects one of up to 3 argument sets (fused QKV).
// Epilogue modes: 0 = fp32 row-major
//                 1 = Q: (acc+bias)/8 -> fp16 hi [bh][s][dk]
//                 2 = K: (acc+bias)   -> fp16 hi/lo [bh][s][dk]
//                 3 = V: (acc+bias)   -> fp16 hi/lo TRANSPOSED [bh][dk][s]
// ---------------------------------------------------------------------------
#define TS_    10240          // one tile: 128 rows * 80 B
#define STAGE_ (3*TS_)        // 30720 per stage (Ah, Bh, Bl)
#define NSTG   3

struct GemmArgs {
    const __half *A, *Bh, *Bl;
    const float* bias;
    float* outf;
    __half *outh, *outl;
    int mode;
};

__global__ __launch_bounds__(256, 2) void gemm_mma(
    GemmArgs ga0, GemmArgs ga1, GemmArgs ga2)
{
    const GemmArgs& G = (blockIdx.z == 0) ? ga0 : (blockIdx.z == 1) ? ga1 : ga2;

    extern __shared__ __align__(128) char smem[];
    const uint32_t sb = smem_u32(smem);
    const int tid = threadIdx.x, warp = tid >> 5, lane = tid & 31;
    const int wm = warp & 3, wn = warp >> 2;
    const int bm = blockIdx.y * 128, bn = blockIdx.x * 128;

    const char* src[3] = {
        (const char*)(G.A  + (size_t)bm * DM_),
        (const char*)(G.Bh + (size_t)bn * DM_),
        (const char*)(G.Bl + (size_t)bn * DM_) };

    float acc[2][8][4];
    #pragma unroll
    for (int mi = 0; mi < 2; ++mi)
        #pragma unroll
        for (int nj = 0; nj < 8; ++nj)
            #pragma unroll
            for (int e = 0; e < 4; ++e) acc[mi][nj][e] = 0.0f;

    const uint32_t offA = (uint32_t)((lane & 15) * 80 + (lane >> 4) * 16);
    const uint32_t offB = (uint32_t)(((((lane >> 4) & 1) * 8) + (lane & 7)) * 80
                                     + ((lane >> 3) & 1) * 16);

    const int lrow = tid >> 2;            // 0..63 (it covers 128)
    const int lseg = (tid & 3) * 16;

    // ---- prologue: stage chunks 0 and 1 ----
    #pragma unroll
    for (int pc = 0; pc < 2; ++pc) {
        const uint32_t stg = pc * STAGE_;
        const int kb = pc * 64;
        #pragma unroll
        for (int t = 0; t < 3; ++t)
            #pragma unroll
            for (int it = 0; it < 2; ++it) {
                int row = lrow + it * 64;
                cp16(sb + stg + t * TS_ + row * 80 + lseg,
                     src[t] + (size_t)row * 2048 + kb + lseg);
            }
        asm volatile("cp.async.commit_group;");
    }

    #pragma unroll 1
    for (int chunk = 0; chunk < 32; ++chunk) {
        if (chunk < 31) asm volatile("cp.async.wait_group 1;");
        else            asm volatile("cp.async.wait_group 0;");
        __syncthreads();

        // issue chunk+2 into the stage freed by chunk-1
        if (chunk + 2 < 32) {
            const uint32_t stg = ((chunk + 2) % NSTG) * STAGE_;
            const int kb = (chunk + 2) * 64;
            #pragma unroll
            for (int t = 0; t < 3; ++t)
                #pragma unroll
                for (int it = 0; it < 2; ++it) {
                    int row = lrow + it * 64;
                    cp16(sb + stg + t * TS_ + row * 80 + lseg,
                         src[t] + (size_t)row * 2048 + kb + lseg);
                }
            asm volatile("cp.async.commit_group;");
        }

        const uint32_t stage = sb + (chunk % NSTG) * STAGE_;
        const uint32_t aHi = stage + 0 * TS_ + wm * 32 * 80 + offA;
        const uint32_t bHi = stage + 1 * TS_ + wn * 64 * 80 + offB;
        const uint32_t bLo = stage + 2 * TS_ + wn * 64 * 80 + offB;

        #pragma unroll
        for (int ks = 0; ks < 2; ++ks) {
            uint32_t rah[2][4], rb[4][4];
            ldsm4(rah[0], aHi + ks * 32);
            ldsm4(rah[1], aHi + 16 * 80 + ks * 32);
            #pragma unroll
            for (int j = 0; j < 4; ++j)
                ldsm4(rb[j], bHi + j * 16 * 80 + ks * 32);
            #pragma unroll
            for (int mi = 0; mi < 2; ++mi)
                #pragma unroll
                for (int nj = 0; nj < 8; ++nj)
                    mma_f16(acc[mi][nj], rah[mi], &rb[nj >> 1][(nj & 1) * 2]);
            #pragma unroll
            for (int j = 0; j < 4; ++j)
                ldsm4(rb[j], bLo + j * 16 * 80 + ks * 32);
            #pragma unroll
            for (int mi = 0; mi < 2; ++mi)
                #pragma unroll
                for (int nj = 0; nj < 8; ++nj)
                    mma_f16(acc[mi][nj], rah[mi], &rb[nj >> 1][(nj & 1) * 2]);
        }
    }

    // ---- epilogue ----
    const int r0 = bm + wm * 32 + (lane >> 2);
    const int c0 = bn + wn * 64 + (lane & 3) * 2;
    const int mode = G.mode;
    const float sc = (mode == 1) ? 0.125f : 1.0f;
    #pragma unroll
    for (int mi = 0; mi < 2; ++mi) {
        #pragma unroll
        for (int nj = 0; nj < 8; ++nj) {
            const int gc = c0 + nj * 8;
            const float bx = G.bias[gc], by = G.bias[gc + 1];
            #pragma unroll
            for (int half = 0; half < 2; ++half) {
                const int row = r0 + mi * 16 + half * 8;
                float vx = acc[mi][nj][half * 2 + 0] + bx;
                float vy = acc[mi][nj][half * 2 + 1] + by;
                if (mode == 0) {
                    float2 v = make_float2(vx, vy);
                    *(float2*)&G.outf[(size_t)row * DM_ + gc] = v;
                } else {
                    vx *= sc; vy *= sc;
                    const int bb = row >> 10, ss = row & 1023;
                    const int hh = gc >> 6, dk = gc & 63;
                    if (mode == 1) {
                        size_t idx = (((size_t)(bb * H_ + hh)) * S_ + ss) * DK_ + dk;
                        *(uint32_t*)&G.outh[idx] = pack2h(vx, vy);
                    } else if (mode == 2) {
                        uint32_t hp, lp;
                        split_pack2h(vx, vy, hp, lp);
                        size_t idx = (((size_t)(bb * H_ + hh)) * S_ + ss) * DK_ + dk;
                        *(uint32_t*)&G.outh[idx] = hp;
                        *(uint32_t*)&G.outl[idx] = lp;
                    } else {
                        __half hx, lx, hy, ly;
                        split1h(vx, hx, lx);
                        split1h(vy, hy, ly);
                        size_t idx = (((size_t)(bb * H_ + hh)) * DK_ + dk) * S_ + ss;
                        G.outh[idx] = hx;         G.outl[idx] = lx;
                        G.outh[idx + S_] = hy;    G.outl[idx + S_] = ly;
                    }
                }
            }
        }
    }
}

// ---------------------------------------------------------------------------
// FlashAttention-2 on mma.sync fp16, 2-term (hi-A x hi/lo-B) for QK^T and PV.
// CTA: 128 q-rows x 8 warps (m16 each), K-tiles of 64 keys, double-buffered.
// ---------------------------------------------------------------------------
#define RB    144            // smem row: 64 fp16 = 128B data + 16B pad
#define TILEB (64*RB)        // 9216
#define BUFB  (4*TILEB)      // 36864 (kh, kl, vh, vl)

__global__ __launch_bounds__(256) void attn_mma(
    const __half* __restrict__ pqh,
    const __half* __restrict__ pkh, const __half* __restrict__ pkl,
    const __half* __restrict__ pvh, const __half* __restrict__ pvl,
    __half* __restrict__ och)
{
    extern __shared__ __align__(128) char smem[];
    const uint32_t sb = smem_u32(smem);
    const int tid = threadIdx.x, w = tid >> 5, lane = tid & 31;
    const int bh = blockIdx.y, b = bh >> 4, h = bh & 15;
    const int row0 = blockIdx.x * 128;

    const uint32_t offA = (uint32_t)((lane & 15) * RB + (lane >> 4) * 16);
    const uint32_t offB = (uint32_t)(((((lane >> 4) & 1) * 8) + (lane & 7)) * RB
                                     + ((lane >> 3) & 1) * 16);

    // ---- stage Q (hi only), extract A fragments ----
    {
        const char* q_src = (const char*)(pqh + ((size_t)bh * S_ + row0) * DK_);
        #pragma unroll
        for (int i = 0; i < 4; ++i) {
            int idx = tid + i * 256;            // 0..1023
            int row = idx >> 3, seg = idx & 7;
            cp16(sb + row * RB + seg * 16, q_src + (size_t)row * 128 + seg * 16);
        }
        asm volatile("cp.async.commit_group;");
        asm volatile("cp.async.wait_group 0;");
        __syncthreads();
    }
    uint32_t qf[4][4];
    #pragma unroll
    for (int ks = 0; ks < 4; ++ks)
        ldsm4(qf[ks], sb + w * 16 * RB + offA + ks * 32);
    __syncthreads();

    float oacc[8][4];
    #pragma unroll
    for (int j = 0; j < 8; ++j)
        #pragma unroll
        for (int e = 0; e < 4; ++e) oacc[j][e] = 0.0f;
    float m0 = -INFINITY, m1 = -INFINITY, l0 = 0.0f, l1 = 0.0f;

    const char* kh_src = (const char*)(pkh + (size_t)bh * S_ * DK_);
    const char* kl_src = (const char*)(pkl + (size_t)bh * S_ * DK_);
    const char* vh_src = (const char*)(pvh + (size_t)bh * DK_ * S_);
    const char* vl_src = (const char*)(pvl + (size_t)bh * DK_ * S_);

    // prefetch K-tile 0
    #pragma unroll
    for (int i = 0; i < 8; ++i) {
        int idx = tid + i * 256;
        int tile = idx >> 9, rem = idx & 511, row = rem >> 3, seg = rem & 7;
        const char* s;
        if (tile == 0)      s = kh_src + (size_t)row * 128 + seg * 16;
        else if (tile == 1) s = kl_src + (size_t)row * 128 + seg * 16;
        else if (tile == 2) s = vh_src + (size_t)row * 2048 + seg * 16;
        else                s = vl_src + (size_t)row * 2048 + seg * 16;
        cp16(sb + tile * TILEB + row * RB + seg * 16, s);
    }
    asm volatile("cp.async.commit_group;");

    #pragma unroll 1
    for (int t = 0; t < 16; ++t) {
        asm volatile("cp.async.wait_group 0;");
        __syncthreads();
        const uint32_t buf = sb + (t & 1) * BUFB;
        if (t < 15) {
            const uint32_t nbuf = sb + ((t + 1) & 1) * BUFB;
            const int kb = (t + 1) * 64;
            #pragma unroll
            for (int i = 0; i < 8; ++i) {
                int idx = tid + i * 256;
                int tile = idx >> 9, rem = idx & 511, row = rem >> 3, seg = rem & 7;
                const char* s;
                if (tile == 0)      s = kh_src + (size_t)(kb + row) * 128 + seg * 16;
                else if (tile == 1) s = kl_src + (size_t)(kb + row) * 128 + seg * 16;
                else if (tile == 2) s = vh_src + (size_t)row * 2048 + kb * 2 + seg * 16;
                else                s = vl_src + (size_t)row * 2048 + kb * 2 + seg * 16;
                cp16(nbuf + tile * TILEB + row * RB + seg * 16, s);
            }
            asm volatile("cp.async.commit_group;");
        }

        // ---- S = Q K^T (2-term: Qh*Kh + Qh*Kl) ----
        float sa[8][4];
        #pragma unroll
        for (int j = 0; j < 8; ++j)
            #pragma unroll
            for (int e = 0; e < 4; ++e) sa[j][e] = 0.0f;

        #pragma unroll
        for (int ks = 0; ks < 4; ++ks) {
            #pragma unroll
            for (int np = 0; np < 4; ++np) {
                uint32_t f[4], g[4];
                ldsm4(f, buf + np * 16 * RB + offB + ks * 32);
                mma_f16(sa[2*np],   qf[ks], f);
                mma_f16(sa[2*np+1], qf[ks], f + 2);
                ldsm4(g, buf + TILEB + np * 16 * RB + offB + ks * 32);
                mma_f16(sa[2*np],   qf[ks], g);
                mma_f16(sa[2*np+1], qf[ks], g + 2);
            }
        }

        // ---- mask + online softmax ----
        float mx0 = -INFINITY, mx1 = -INFINITY;
        #pragma unroll
        for (int j = 0; j < 8; ++j) {
            #pragma unroll
            for (int e = 0; e < 4; ++e)
                if (sa[j][e] == 0.0f) sa[j][e] = -INFINITY;
            mx0 = fmaxf(mx0, fmaxf(sa[j][0], sa[j][1]));
            mx1 = fmaxf(mx1, fmaxf(sa[j][2], sa[j][3]));
        }
        mx0 = fmaxf(mx0, __shfl_xor_sync(0xffffffffu, mx0, 1));
        mx0 = fmaxf(mx0, __shfl_xor_sync(0xffffffffu, mx0, 2));
        mx1 = fmaxf(mx1, __shfl_xor_sync(0xffffffffu, mx1, 1));
        mx1 = fmaxf(mx1, __shfl_xor_sync(0xffffffffu, mx1, 2));

        float mn0 = fmaxf(fmaxf(m0, mx0), -1e30f);
        float mn1 = fmaxf(fmaxf(m1, mx1), -1e30f);
        float a0 = __expf(m0 - mn0), a1 = __expf(m1 - mn1);
        m0 = mn0; m1 = mn1;

        float rs0 = 0.0f, rs1 = 0.0f;
        #pragma unroll
        for (int j = 0; j < 8; ++j) {
            sa[j][0] = __expf(sa[j][0] - m0);
            sa[j][1] = __expf(sa[j][1] - m0);
            sa[j][2] = __expf(sa[j][2] - m1);
            sa[j][3] = __expf(sa[j][3] - m1);
            rs0 += sa[j][0] + sa[j][1];
            rs1 += sa[j][2] + sa[j][3];
        }
        rs0 += __shfl_xor_sync(0xffffffffu, rs0, 1);
        rs0 += __shfl_xor_sync(0xffffffffu, rs0, 2);
        rs1 += __shfl_xor_sync(0xffffffffu, rs1, 1);
        rs1 += __shfl_xor_sync(0xffffffffu, rs1, 2);
        l0 = l0 * a0 + rs0;
        l1 = l1 * a1 + rs1;

        #pragma unroll
        for (int j = 0; j < 8; ++j) {
            oacc[j][0] *= a0; oacc[j][1] *= a0;
            oacc[j][2] *= a1; oacc[j][3] *= a1;
        }

        // ---- P fragments (hi only) ----
        uint32_t ph[4][4];
        #pragma unroll
        for (int tt = 0; tt < 4; ++tt) {
            ph[tt][0] = pack2h(sa[2*tt][0],   sa[2*tt][1]);
            ph[tt][1] = pack2h(sa[2*tt][2],   sa[2*tt][3]);
            ph[tt][2] = pack2h(sa[2*tt+1][0], sa[2*tt+1][1]);
            ph[tt][3] = pack2h(sa[2*tt+1][2], sa[2*tt+1][3]);
        }

        // ---- O += P V (2-term: Ph*Vh + Ph*Vl), V^T tiles ----
        #pragma unroll
        for (int ks = 0; ks < 4; ++ks) {
            #pragma unroll
            for (int np = 0; np < 4; ++np) {
                uint32_t f[4], g[4];
                ldsm4(f, buf + 2 * TILEB + np * 16 * RB + offB + ks * 32);
                mma_f16(oacc[2*np],   ph[ks], f);
                mma_f16(oacc[2*np+1], ph[ks], f + 2);
                ldsm4(g, buf + 3 * TILEB + np * 16 * RB + offB + ks * 32);
                mma_f16(oacc[2*np],   ph[ks], g);
                mma_f16(oacc[2*np+1], ph[ks], g + 2);
            }
        }
    }

    // ---- normalize + store (concat layout, fp16 hi) ----
    const float i0 = 1.0f / l0, i1 = 1.0f / l1;
    const int r = lane >> 2, c = (lane & 3) * 2;
    const int grow0 = row0 + w * 16 + r;
    const size_t base0 = ((size_t)b * S_ + grow0) * DM_ + h * DK_;
    const size_t base1 = ((size_t)b * S_ + grow0 + 8) * DM_ + h * DK_;
    #pragma unroll
    for (int nt = 0; nt < 8; ++nt) {
        const int gc = nt * 8 + c;
        *(uint32_t*)&och[base0 + gc] = pack2h(oacc[nt][0] * i0, oacc[nt][1] * i0);
        *(uint32_t*)&och[base1 + gc] = pack2h(oacc[nt][2] * i1, oacc[nt][3] * i1);
    }
}

// ---------------------------------------------------------------------------

extern "C" void kernel_launch(void* const* d_in, const int* in_sizes, int n_in,
                              void* d_out, int out_size)
{
    const float* q  = (const float*)d_in[0];
    const float* k  = (const float*)d_in[1];
    const float* v  = (const float*)d_in[2];
    const float* Wq = (const float*)d_in[3];
    const float* bq = (const float*)d_in[4];
    const float* Wk = (const float*)d_in[5];
    const float* bk = (const float*)d_in[6];
    const float* Wv = (const float*)d_in[7];
    const float* bv = (const float*)d_in[8];
    const float* Wf = (const float*)d_in[9];
    const float* bf = (const float*)d_in[10];
    float* out = (float*)d_out;

    __half *xqh, *xkh, *xvh;
    __half *pqh, *pkh, *pkl, *pvh, *pvl, *och;
    __half *wqh, *wql, *wkh, *wkl, *wvh, *wvl, *wfh, *wfl;
    cudaGetSymbolAddress((void**)&xqh, g_xqh);
    cudaGetSymbolAddress((void**)&xkh, g_xkh);
    cudaGetSymbolAddress((void**)&xvh, g_xvh);
    cudaGetSymbolAddress((void**)&pqh, g_pqh);
    cudaGetSymbolAddress((void**)&pkh, g_pkh); cudaGetSymbolAddress((void**)&pkl, g_pkl);
    cudaGetSymbolAddress((void**)&pvh, g_pvh); cudaGetSymbolAddress((void**)&pvl, g_pvl);
    cudaGetSymbolAddress((void**)&och, g_och);
    cudaGetSymbolAddress((void**)&wqh, g_wqh); cudaGetSymbolAddress((void**)&wql, g_wql);
    cudaGetSymbolAddress((void**)&wkh, g_wkh); cudaGetSymbolAddress((void**)&wkl, g_wkl);
    cudaGetSymbolAddress((void**)&wvh, g_wvh); cudaGetSymbolAddress((void**)&wvl, g_wvl);
    cudaGetSymbolAddress((void**)&wfh, g_wfh); cudaGetSymbolAddress((void**)&wfl, g_wfl);

    conv_fp16_b<<<dim3(NE/4/256, 3), 256>>>(q, xqh, k, xkh, v, xvh, NE/4);
    split_fp16_b<<<dim3(NW/4/256, 4), 256>>>(
        Wq, wqh, wql,  Wk, wkh, wkl,  Wv, wvh, wvl,  Wf, wfh, wfl, NW/4);

    const int gemm_smem = NSTG * STAGE_;   // 92160
    cudaFuncSetAttribute(gemm_mma, cudaFuncAttributeMaxDynamicSharedMemorySize, gemm_smem);

    GemmArgs gq = { xqh, wqh, wql, bq, nullptr, pqh, nullptr, 1 };
    GemmArgs gk = { xkh, wkh, wkl, bk, nullptr, pkh, pkl, 2 };
    GemmArgs gv = { xvh, wvh, wvl, bv, nullptr, pvh, pvl, 3 };
    GemmArgs gf = { och, wfh, wfl, bf, out, nullptr, nullptr, 0 };

    // fused QKV projections: one launch, blockIdx.z = tensor
    gemm_mma<<<dim3(DM_/128, M_/128, 3), 256, gemm_smem>>>(gq, gk, gv);

    const int attn_smem = 2 * BUFB;     // 73728
    cudaFuncSetAttribute(attn_mma, cudaFuncAttributeMaxDynamicSharedMemorySize, attn_smem);
    attn_mma<<<dim3(S_/128, B_*H_), 256, attn_smem>>>(
        pqh, pkh, pkl, pvh, pvl, och);

    gemm_mma<<<dim3(DM_/128, M_/128, 1), 256, gemm_smem>>>(gf, gf, gf);
}

// round 17
// speedup vs baseline: 3.4428x; 1.1748x over previous
#include <cuda_runtime.h>
#include <cuda_fp16.h>
#include <math.h>
#include <stdint.h>

#define B_  8
#define H_  16
#define S_  1024
#define DK_ 64
#define DM_ 1024
#define M_  (B_*S_)          // 8192
#define NE  (M_*DM_)         // 8M activation elems
#define NW  (DM_*DM_)        // 1M weight elems

// ---- scratch (allocation-free rule: __device__ globals) --------------------
__device__ __half g_xqh[NE], g_xkh[NE], g_xvh[NE];
__device__ __half g_pqh[NE];               // Q/8   [bh][s][dk]  hi only
__device__ __half g_pkh[NE], g_pkl[NE];    // K     [bh][s][dk]  hi/lo
__device__ __half g_pvh[NE];               // V^T   [bh][dk][s]  hi only
__device__ __half g_och[NE];               // attention out (concat), hi only
__device__ __half g_wqh[NW], g_wql[NW];
__device__ __half g_wkh[NW], g_wkl[NW];
__device__ __half g_wvh[NW], g_wvl[NW];
__device__ __half g_wfh[NW];               // final weights hi only (1-term)

// ---- helpers ---------------------------------------------------------------
__device__ __forceinline__ uint32_t smem_u32(const void* p) {
    uint32_t a;
    asm("{ .reg .u64 t; cvta.to.shared.u64 t, %1; cvt.u32.u64 %0, t; }"
        : "=r"(a) : "l"(p));
    return a;
}

__device__ __forceinline__ void cp16(uint32_t dst, const void* src) {
    asm volatile("cp.async.cg.shared.global [%0], [%1], 16;"
                 :: "r"(dst), "l"(src));
}

__device__ __forceinline__ void ldsm4(uint32_t* r, uint32_t addr) {
    asm volatile("ldmatrix.sync.aligned.m8n8.x4.shared.b16 {%0,%1,%2,%3}, [%4];"
                 : "=r"(r[0]), "=r"(r[1]), "=r"(r[2]), "=r"(r[3]) : "r"(addr));
}

__device__ __forceinline__ void mma_f16(float* d, const uint32_t* a, const uint32_t* b) {
    asm volatile(
        "mma.sync.aligned.m16n8k16.row.col.f32.f16.f16.f32 "
        "{%0,%1,%2,%3}, {%4,%5,%6,%7}, {%8,%9}, {%0,%1,%2,%3};"
        : "+f"(d[0]), "+f"(d[1]), "+f"(d[2]), "+f"(d[3])
        : "r"(a[0]), "r"(a[1]), "r"(a[2]), "r"(a[3]), "r"(b[0]), "r"(b[1]));
}

__device__ __forceinline__ uint32_t pack2h(float x, float y) {
    __half2 t = __halves2half2(__float2half_rn(x), __float2half_rn(y));
    return *(uint32_t*)&t;
}

__device__ __forceinline__ void split1h(float v, __half& h, __half& l) {
    h = __float2half_rn(v);
    l = __float2half_rn(v - __half2float(h));
}

__device__ __forceinline__ void split_pack2h(float x, float y, uint32_t& hi, uint32_t& lo) {
    __half hx, lx, hy, ly;
    split1h(x, hx, lx);
    split1h(y, hy, ly);
    __half2 th = __halves2half2(hx, hy);
    __half2 tl = __halves2half2(lx, ly);
    hi = *(uint32_t*)&th;
    lo = *(uint32_t*)&tl;
}

// ---------------------------------------------------------------------------
// activations + Wf: fp32 -> fp16 (hi only), 4 independent float4/thread (MLP).
// blockIdx.y selects tensor (0..2 = q,k,v with n4a; 3 = Wf with n4w).
// ---------------------------------------------------------------------------
__global__ __launch_bounds__(256) void conv_fp16_b(
    const float* __restrict__ x0, __half* __restrict__ h0,
    const float* __restrict__ x1, __half* __restrict__ h1,
    const float* __restrict__ x2, __half* __restrict__ h2,
    const float* __restrict__ x3, __half* __restrict__ h3,
    int n4a, int n4w)
{
    const float* x;
    __half* hi;
    int n4;
    switch (blockIdx.y) {
        case 0: x = x0; hi = h0; n4 = n4a; break;
        case 1: x = x1; hi = h1; n4 = n4a; break;
        case 2: x = x2; hi = h2; n4 = n4a; break;
        default: x = x3; hi = h3; n4 = n4w; break;
    }
    const int stride = n4 >> 2;
    int i = blockIdx.x * blockDim.x + threadIdx.x;
    if (i >= stride) return;
    float4 v0 = ((const float4*)x)[i];
    float4 v1 = ((const float4*)x)[i + stride];
    float4 v2 = ((const float4*)x)[i + 2 * stride];
    float4 v3 = ((const float4*)x)[i + 3 * stride];
    ((uint32_t*)hi)[2*i]                    = pack2h(v0.x, v0.y);
    ((uint32_t*)hi)[2*i + 1]                = pack2h(v0.z, v0.w);
    ((uint32_t*)hi)[2*(i + stride)]         = pack2h(v1.x, v1.y);
    ((uint32_t*)hi)[2*(i + stride) + 1]     = pack2h(v1.z, v1.w);
    ((uint32_t*)hi)[2*(i + 2*stride)]       = pack2h(v2.x, v2.y);
    ((uint32_t*)hi)[2*(i + 2*stride) + 1]   = pack2h(v2.z, v2.w);
    ((uint32_t*)hi)[2*(i + 3*stride)]       = pack2h(v3.x, v3.y);
    ((uint32_t*)hi)[2*(i + 3*stride) + 1]   = pack2h(v3.z, v3.w);
}

// ---------------------------------------------------------------------------
// QKV weights: fp32 -> (fp16 hi, fp16 lo), 4 float4/thread. blockIdx.y 0..2.
// ---------------------------------------------------------------------------
__global__ __launch_bounds__(256) void split_fp16_b(
    const float* __restrict__ x0, __half* __restrict__ h0, __half* __restrict__ l0m,
    const float* __restrict__ x1, __half* __restrict__ h1, __half* __restrict__ l1m,
    const float* __restrict__ x2, __half* __restrict__ h2, __half* __restrict__ l2m,
    int n4)
{
    const float* x;
    __half *hi, *lo;
    switch (blockIdx.y) {
        case 0: x = x0; hi = h0; lo = l0m; break;
        case 1: x = x1; hi = h1; lo = l1m; break;
        default: x = x2; hi = h2; lo = l2m; break;
    }
    const int stride = n4 >> 2;
    int i = blockIdx.x * blockDim.x + threadIdx.x;
    if (i >= stride) return;
    #pragma unroll
    for (int p = 0; p < 4; ++p) {
        int idx = i + p * stride;
        float4 v = ((const float4*)x)[idx];
        uint32_t ha, la, hb, lb;
        split_pack2h(v.x, v.y, ha, la);
        split_pack2h(v.z, v.w, hb, lb);
        ((uint32_t*)hi)[2*idx]     = ha;
        ((uint32_t*)hi)[2*idx + 1] = hb;
        ((uint32_t*)lo)[2*idx]     = la;
        ((uint32_t*)lo)[2*idx + 1] = lb;
    }
}

// ---------------------------------------------------------------------------
// GEMM via mma.sync fp16: C = Ah*(Bh[+Bl])^T (+bias); terms = 1 or 2.
// 128x128 C-tile / CTA; BK=32; 8 warps (4M x 2N); warp tile 32x64.
// 3-stage cp.async pipeline; blockIdx.z selects arg set (fused QKV).
// Epilogue modes: 0 = fp32 row-major
//                 1 = Q: (acc+bias)/8 -> fp16 hi [bh][s][dk]
//                 2 = K: (acc+bias)   -> fp16 hi/lo [bh][s][dk]
//                 3 = V: (acc+bias)   -> fp16 hi TRANSPOSED [bh][dk][s]
// ---------------------------------------------------------------------------
#define TS_    10240          // one tile: 128 rows * 80 B
#define STAGE_ (3*TS_)        // 30720 per stage (Ah, Bh, Bl)
#define NSTG   3

struct GemmArgs {
    const __half *A, *Bh, *Bl;
    const float* bias;
    float* outf;
    __half *outh, *outl;
    int mode;
    int terms;
};

__global__ __launch_bounds__(256, 2) void gemm_mma(
    GemmArgs ga0, GemmArgs ga1, GemmArgs ga2)
{
    const GemmArgs& G = (blockIdx.z == 0) ? ga0 : (blockIdx.z == 1) ? ga1 : ga2;

    extern __shared__ __align__(128) char smem[];
    const uint32_t sb = smem_u32(smem);
    const int tid = threadIdx.x, warp = tid >> 5, lane = tid & 31;
    const int wm = warp & 3, wn = warp >> 2;
    const int bm = blockIdx.y * 128, bn = blockIdx.x * 128;
    const int terms = G.terms;

    const char* src[3] = {
        (const char*)(G.A  + (size_t)bm * DM_),
        (const char*)(G.Bh + (size_t)bn * DM_),
        (const char*)(G.Bl + (size_t)bn * DM_) };

    float acc[2][8][4];
    #pragma unroll
    for (int mi = 0; mi < 2; ++mi)
        #pragma unroll
        for (int nj = 0; nj < 8; ++nj)
            #pragma unroll
            for (int e = 0; e < 4; ++e) acc[mi][nj][e] = 0.0f;

    const uint32_t offA = (uint32_t)((lane & 15) * 80 + (lane >> 4) * 16);
    const uint32_t offB = (uint32_t)(((((lane >> 4) & 1) * 8) + (lane & 7)) * 80
                                     + ((lane >> 3) & 1) * 16);

    const int lrow = tid >> 2;            // 0..63 (it covers 128)
    const int lseg = (tid & 3) * 16;

    // ---- prologue: stage chunks 0 and 1 ----
    #pragma unroll
    for (int pc = 0; pc < 2; ++pc) {
        const uint32_t stg = pc * STAGE_;
        const int kb = pc * 64;
        #pragma unroll
        for (int t = 0; t < 3; ++t) {
            if (t == 2 && terms == 1) continue;
            #pragma unroll
            for (int it = 0; it < 2; ++it) {
                int row = lrow + it * 64;
                cp16(sb + stg + t * TS_ + row * 80 + lseg,
                     src[t] + (size_t)row * 2048 + kb + lseg);
            }
        }
        asm volatile("cp.async.commit_group;");
    }

    #pragma unroll 1
    for (int chunk = 0; chunk < 32; ++chunk) {
        if (chunk < 31) asm volatile("cp.async.wait_group 1;");
        else            asm volatile("cp.async.wait_group 0;");
        __syncthreads();

        // issue chunk+2 into the stage freed by chunk-1
        if (chunk + 2 < 32) {
            const uint32_t stg = ((chunk + 2) % NSTG) * STAGE_;
            const int kb = (chunk + 2) * 64;
            #pragma unroll
            for (int t = 0; t < 3; ++t) {
                if (t == 2 && terms == 1) continue;
                #pragma unroll
                for (int it = 0; it < 2; ++it) {
                    int row = lrow + it * 64;
                    cp16(sb + stg + t * TS_ + row * 80 + lseg,
                         src[t] + (size_t)row * 2048 + kb + lseg);
                }
            }
            asm volatile("cp.async.commit_group;");
        }

        const uint32_t stage = sb + (chunk % NSTG) * STAGE_;
        const uint32_t aHi = stage + 0 * TS_ + wm * 32 * 80 + offA;
        const uint32_t bHi = stage + 1 * TS_ + wn * 64 * 80 + offB;
        const uint32_t bLo = stage + 2 * TS_ + wn * 64 * 80 + offB;

        #pragma unroll
        for (int ks = 0; ks < 2; ++ks) {
            uint32_t rah[2][4], rb[4][4];
            ldsm4(rah[0], aHi + ks * 32);
            ldsm4(rah[1], aHi + 16 * 80 + ks * 32);
            #pragma unroll
            for (int j = 0; j < 4; ++j)
                ldsm4(rb[j], bHi + j * 16 * 80 + ks * 32);
            #pragma unroll
            for (int mi = 0; mi < 2; ++mi)
                #pragma unroll
                for (int nj = 0; nj < 8; ++nj)
                    mma_f16(acc[mi][nj], rah[mi], &rb[nj >> 1][(nj & 1) * 2]);
            if (terms == 2) {
                #pragma unroll
                for (int j = 0; j < 4; ++j)
                    ldsm4(rb[j], bLo + j * 16 * 80 + ks * 32);
                #pragma unroll
                for (int mi = 0; mi < 2; ++mi)
                    #pragma unroll
                    for (int nj = 0; nj < 8; ++nj)
                        mma_f16(acc[mi][nj], rah[mi], &rb[nj >> 1][(nj & 1) * 2]);
            }
        }
    }

    // ---- epilogue ----
    const int r0 = bm + wm * 32 + (lane >> 2);
    const int c0 = bn + wn * 64 + (lane & 3) * 2;
    const int mode = G.mode;
    const float sc = (mode == 1) ? 0.125f : 1.0f;
    #pragma unroll
    for (int mi = 0; mi < 2; ++mi) {
        #pragma unroll
        for (int nj = 0; nj < 8; ++nj) {
            const int gc = c0 + nj * 8;
            const float bx = G.bias[gc], by = G.bias[gc + 1];
            #pragma unroll
            for (int half = 0; half < 2; ++half) {
                const int row = r0 + mi * 16 + half * 8;
                float vx = acc[mi][nj][half * 2 + 0] + bx;
                float vy = acc[mi][nj][half * 2 + 1] + by;
                if (mode == 0) {
                    float2 v = make_float2(vx, vy);
                    *(float2*)&G.outf[(size_t)row * DM_ + gc] = v;
                } else {
                    vx *= sc; vy *= sc;
                    const int bb = row >> 10, ss = row & 1023;
                    const int hh = gc >> 6, dk = gc & 63;
                    if (mode == 1) {
                        size_t idx = (((size_t)(bb * H_ + hh)) * S_ + ss) * DK_ + dk;
                        *(uint32_t*)&G.outh[idx] = pack2h(vx, vy);
                    } else if (mode == 2) {
                        uint32_t hp, lp;
                        split_pack2h(vx, vy, hp, lp);
                        size_t idx = (((size_t)(bb * H_ + hh)) * S_ + ss) * DK_ + dk;
                        *(uint32_t*)&G.outh[idx] = hp;
                        *(uint32_t*)&G.outl[idx] = lp;
                    } else {
                        size_t idx = (((size_t)(bb * H_ + hh)) * DK_ + dk) * S_ + ss;
                        G.outh[idx]      = __float2half_rn(vx);
                        G.outh[idx + S_] = __float2half_rn(vy);
                    }
                }
            }
        }
    }
}

// ---------------------------------------------------------------------------
// FlashAttention-2 on mma.sync fp16: QK^T 2-term (Kh+Kl), PV 1-term (Vh).
// CTA: 128 q-rows x 8 warps (m16 each), K-tiles of 64 keys, double-buffered.
// smem tiles per buffer: kh, kl, vh (3 x 9216 = 27648; 2 buffers = 55296).
// ---------------------------------------------------------------------------
#define RB    144            // smem row: 64 fp16 = 128B data + 16B pad
#define TILEB (64*RB)        // 9216
#define BUFB  (3*TILEB)      // 27648 (kh, kl, vh)

__global__ __launch_bounds__(256) void attn_mma(
    const __half* __restrict__ pqh,
    const __half* __restrict__ pkh, const __half* __restrict__ pkl,
    const __half* __restrict__ pvh,
    __half* __restrict__ och)
{
    extern __shared__ __align__(128) char smem[];
    const uint32_t sb = smem_u32(smem);
    const int tid = threadIdx.x, w = tid >> 5, lane = tid & 31;
    const int bh = blockIdx.y, b = bh >> 4, h = bh & 15;
    const int row0 = blockIdx.x * 128;

    const uint32_t offA = (uint32_t)((lane & 15) * RB + (lane >> 4) * 16);
    const uint32_t offB = (uint32_t)(((((lane >> 4) & 1) * 8) + (lane & 7)) * RB
                                     + ((lane >> 3) & 1) * 16);

    // ---- stage Q (hi only), extract A fragments ----
    {
        const char* q_src = (const char*)(pqh + ((size_t)bh * S_ + row0) * DK_);
        #pragma unroll
        for (int i = 0; i < 4; ++i) {
            int idx = tid + i * 256;            // 0..1023
            int row = idx >> 3, seg = idx & 7;
            cp16(sb + row * RB + seg * 16, q_src + (size_t)row * 128 + seg * 16);
        }
        asm volatile("cp.async.commit_group;");
        asm volatile("cp.async.wait_group 0;");
        __syncthreads();
    }
    uint32_t qf[4][4];
    #pragma unroll
    for (int ks = 0; ks < 4; ++ks)
        ldsm4(qf[ks], sb + w * 16 * RB + offA + ks * 32);
    __syncthreads();

    float oacc[8][4];
    #pragma unroll
    for (int j = 0; j < 8; ++j)
        #pragma unroll
        for (int e = 0; e < 4; ++e) oacc[j][e] = 0.0f;
    float m0 = -INFINITY, m1 = -INFINITY, l0 = 0.0f, l1 = 0.0f;

    const char* kh_src = (const char*)(pkh + (size_t)bh * S_ * DK_);
    const char* kl_src = (const char*)(pkl + (size_t)bh * S_ * DK_);
    const char* vh_src = (const char*)(pvh + (size_t)bh * DK_ * S_);

    // prefetch K-tile 0 (3 tiles x 512 segs = 1536 -> 6 per thread)
    #pragma unroll
    for (int i = 0; i < 6; ++i) {
        int idx = tid + i * 256;
        int tile = idx >> 9, rem = idx & 511, row = rem >> 3, seg = rem & 7;
        const char* s;
        if (tile == 0)      s = kh_src + (size_t)row * 128 + seg * 16;
        else if (tile == 1) s = kl_src + (size_t)row * 128 + seg * 16;
        else                s = vh_src + (size_t)row * 2048 + seg * 16;
        cp16(sb + tile * TILEB + row * RB + seg * 16, s);
    }
    asm volatile("cp.async.commit_group;");

    #pragma unroll 1
    for (int t = 0; t < 16; ++t) {
        asm volatile("cp.async.wait_group 0;");
        __syncthreads();
        const uint32_t buf = sb + (t & 1) * BUFB;
        if (t < 15) {
            const uint32_t nbuf = sb + ((t + 1) & 1) * BUFB;
            const int kb = (t + 1) * 64;
            #pragma unroll
            for (int i = 0; i < 6; ++i) {
                int idx = tid + i * 256;
                int tile = idx >> 9, rem = idx & 511, row = rem >> 3, seg = rem & 7;
                const char* s;
                if (tile == 0)      s = kh_src + (size_t)(kb + row) * 128 + seg * 16;
                else if (tile == 1) s = kl_src + (size_t)(kb + row) * 128 + seg * 16;
                else                s = vh_src + (size_t)row * 2048 + kb * 2 + seg * 16;
                cp16(nbuf + tile * TILEB + row * RB + seg * 16, s);
            }
            asm volatile("cp.async.commit_group;");
        }

        // ---- S = Q K^T (2-term: Qh*Kh + Qh*Kl) ----
        float sa[8][4];
        #pragma unroll
        for (int j = 0; j < 8; ++j)
            #pragma unroll
            for (int e = 0; e < 4; ++e) sa[j][e] = 0.0f;

        #pragma unroll
        for (int ks = 0; ks < 4; ++ks) {
            #pragma unroll
            for (int np = 0; np < 4; ++np) {
                uint32_t f[4], g[4];
                ldsm4(f, buf + np * 16 * RB + offB + ks * 32);
                mma_f16(sa[2*np],   qf[ks], f);
                mma_f16(sa[2*np+1], qf[ks], f + 2);
                ldsm4(g, buf + TILEB + np * 16 * RB + offB + ks * 32);
                mma_f16(sa[2*np],   qf[ks], g);
                mma_f16(sa[2*np+1], qf[ks], g + 2);
            }
        }

        // ---- mask + online softmax ----
        float mx0 = -INFINITY, mx1 = -INFINITY;
        #pragma unroll
        for (int j = 0; j < 8; ++j) {
            #pragma unroll
            for (int e = 0; e < 4; ++e)
                if (sa[j][e] == 0.0f) sa[j][e] = -INFINITY;
            mx0 = fmaxf(mx0, fmaxf(sa[j][0], sa[j][1]));
            mx1 = fmaxf(mx1, fmaxf(sa[j][2], sa[j][3]));
        }
        mx0 = fmaxf(mx0, __shfl_xor_sync(0xffffffffu, mx0, 1));
        mx0 = fmaxf(mx0, __shfl_xor_sync(0xffffffffu, mx0, 2));
        mx1 = fmaxf(mx1, __shfl_xor_sync(0xffffffffu, mx1, 1));
        mx1 = fmaxf(mx1, __shfl_xor_sync(0xffffffffu, mx1, 2));

        float mn0 = fmaxf(fmaxf(m0, mx0), -1e30f);
        float mn1 = fmaxf(fmaxf(m1, mx1), -1e30f);
        float a0 = __expf(m0 - mn0), a1 = __expf(m1 - mn1);
        m0 = mn0; m1 = mn1;

        float rs0 = 0.0f, rs1 = 0.0f;
        #pragma unroll
        for (int j = 0; j < 8; ++j) {
            sa[j][0] = __expf(sa[j][0] - m0);
            sa[j][1] = __expf(sa[j][1] - m0);
            sa[j][2] = __expf(sa[j][2] - m1);
            sa[j][3] = __expf(sa[j][3] - m1);
            rs0 += sa[j][0] + sa[j][1];
            rs1 += sa[j][2] + sa[j][3];
        }
        rs0 += __shfl_xor_sync(0xffffffffu, rs0, 1);
        rs0 += __shfl_xor_sync(0xffffffffu, rs0, 2);
        rs1 += __shfl_xor_sync(0xffffffffu, rs1, 1);
        rs1 += __shfl_xor_sync(0xffffffffu, rs1, 2);
        l0 = l0 * a0 + rs0;
        l1 = l1 * a1 + rs1;

        #pragma unroll
        for (int j = 0; j < 8; ++j) {
            oacc[j][0] *= a0; oacc[j][1] *= a0;
            oacc[j][2] *= a1; oacc[j][3] *= a1;
        }

        // ---- P fragments (hi only) ----
        uint32_t ph[4][4];
        #pragma unroll
        for (int tt = 0; tt < 4; ++tt) {
            ph[tt][0] = pack2h(sa[2*tt][0],   sa[2*tt][1]);
            ph[tt][1] = pack2h(sa[2*tt][2],   sa[2*tt][3]);
            ph[tt][2] = pack2h(sa[2*tt+1][0], sa[2*tt+1][1]);
            ph[tt][3] = pack2h(sa[2*tt+1][2], sa[2*tt+1][3]);
        }

        // ---- O += P V (1-term: Ph*Vh), V^T tiles ----
        #pragma unroll
        for (int ks = 0; ks < 4; ++ks) {
            #pragma unroll
            for (int np = 0; np < 4; ++np) {
                uint32_t f[4];
                ldsm4(f, buf + 2 * TILEB + np * 16 * RB + offB + ks * 32);
                mma_f16(oacc[2*np],   ph[ks], f);
                mma_f16(oacc[2*np+1], ph[ks], f + 2);
            }
        }
    }

    // ---- normalize + store (concat layout, fp16 hi) ----
    const float i0 = 1.0f / l0, i1 = 1.0f / l1;
    const int r = lane >> 2, c = (lane & 3) * 2;
    const int grow0 = row0 + w * 16 + r;
    const size_t base0 = ((size_t)b * S_ + grow0) * DM_ + h * DK_;
    const size_t base1 = ((size_t)b * S_ + grow0 + 8) * DM_ + h * DK_;
    #pragma unroll
    for (int nt = 0; nt < 8; ++nt) {
        const int gc = nt * 8 + c;
        *(uint32_t*)&och[base0 + gc] = pack2h(oacc[nt][0] * i0, oacc[nt][1] * i0);
        *(uint32_t*)&och[base1 + gc] = pack2h(oacc[nt][2] * i1, oacc[nt][3] * i1);
    }
}

// ---------------------------------------------------------------------------

extern "C" void kernel_launch(void* const* d_in, const int* in_sizes, int n_in,
                              void* d_out, int out_size)
{
    const float* q  = (const float*)d_in[0];
    const float* k  = (const float*)d_in[1];
    const float* v  = (const float*)d_in[2];
    const float* Wq = (const float*)d_in[3];
    const float* bq = (const float*)d_in[4];
    const float* Wk = (const float*)d_in[5];
    const float* bk = (const float*)d_in[6];
    const float* Wv = (const float*)d_in[7];
    const float* bv = (const float*)d_in[8];
    const float* Wf = (const float*)d_in[9];
    const float* bf = (const float*)d_in[10];
    float* out = (float*)d_out;

    __half *xqh, *xkh, *xvh;
    __half *pqh, *pkh, *pkl, *pvh, *och;
    __half *wqh, *wql, *wkh, *wkl, *wvh, *wvl, *wfh;
    cudaGetSymbolAddress((void**)&xqh, g_xqh);
    cudaGetSymbolAddress((void**)&xkh, g_xkh);
    cudaGetSymbolAddress((void**)&xvh, g_xvh);
    cudaGetSymbolAddress((void**)&pqh, g_pqh);
    cudaGetSymbolAddress((void**)&pkh, g_pkh); cudaGetSymbolAddress((void**)&pkl, g_pkl);
    cudaGetSymbolAddress((void**)&pvh, g_pvh);
    cudaGetSymbolAddress((void**)&och, g_och);
    cudaGetSymbolAddress((void**)&wqh, g_wqh); cudaGetSymbolAddress((void**)&wql, g_wql);
    cudaGetSymbolAddress((void**)&wkh, g_wkh); cudaGetSymbolAddress((void**)&wkl, g_wkl);
    cudaGetSymbolAddress((void**)&wvh, g_wvh); cudaGetSymbolAddress((void**)&wvl, g_wvl);
    cudaGetSymbolAddress((void**)&wfh, g_wfh);

    // activations q,k,v (hi only) + Wf (hi only), MLP=4
    conv_fp16_b<<<dim3(NE/16/256, 4), 256>>>(
        q, xqh, k, xkh, v, xvh, Wf, wfh, NE/4, NW/4);
    // QKV weights hi/lo, MLP=4
    split_fp16_b<<<dim3(NW/16/256, 3), 256>>>(
        Wq, wqh, wql,  Wk, wkh, wkl,  Wv, wvh, wvl, NW/4);

    const int gemm_smem = NSTG * STAGE_;   // 92160
    cudaFuncSetAttribute(gemm_mma, cudaFuncAttributeMaxDynamicSharedMemorySize, gemm_smem);

    GemmArgs gq = { xqh, wqh, wql, bq, nullptr, pqh, nullptr, 1, 2 };
    GemmArgs gk = { xkh, wkh, wkl, bk, nullptr, pkh, pkl, 2, 2 };
    GemmArgs gv = { xvh, wvh, wvl, bv, nullptr, pvh, nullptr, 3, 2 };
    GemmArgs gf = { och, wfh, wfh, bf, out, nullptr, nullptr, 0, 1 };

    // fused QKV projections: one launch, blockIdx.z = tensor
    gemm_mma<<<dim3(DM_/128, M_/128, 3), 256, gemm_smem>>>(gq, gk, gv);

    const int attn_smem = 2 * BUFB;     // 55296
    cudaFuncSetAttribute(attn_mma, cudaFuncAttributeMaxDynamicSharedMemorySize, attn_smem);
    attn_mma<<<dim3(S_/128, B_*H_), 256, attn_smem>>>(
        pqh, pkh, pkl, pvh, och);

    gemm_mma<<<dim3(DM_/128, M_/128, 1), 256, gemm_smem>>>(gf, gf, gf);
}